// round 1
// baseline (speedup 1.0000x reference)
#include <cuda_runtime.h>
#include <math.h>

#define N_NODES 50000
#define N_EDGES 800000
#define HID 128
#define EC 100
#define IN_DIM 5
#define N_BLOCKS 6

// ---------------- scratch (device globals; no runtime allocation) ----------------
__device__ float g_x[N_NODES * HID];     // 25.6 MB
__device__ float g_agg[N_NODES * HID];   // 25.6 MB
__device__ float g_T[(size_t)N_EDGES * HID]; // 409.6 MB
__device__ float g_W[(size_t)N_EDGES * HID]; // 409.6 MB
__device__ float g_C[N_EDGES];           // 3.2 MB

__device__ __forceinline__ float sspf(float x) {
    // softplus(x) - log(2), numerically stable
    float sp = fmaxf(x, 0.0f) + log1pf(expf(-fabsf(x)));
    return sp - 0.69314718055994531f;
}

// ---------------- small kernels ----------------
__global__ void embed_kernel(const float* __restrict__ z, const float* __restrict__ w,
                             const float* __restrict__ b, float* __restrict__ h) {
    int n = blockIdx.x, j = threadIdx.x;
    const float* zr = z + (size_t)n * (IN_DIM + HID);
    float acc = b[j] + zr[IN_DIM + j];
#pragma unroll
    for (int k = 0; k < IN_DIM; k++) acc = fmaf(zr[k], w[k * HID + j], acc);
    h[(size_t)n * HID + j] = acc;
}

__global__ void cmask_kernel(const float* __restrict__ len, float* __restrict__ C) {
    int e = blockIdx.x * 256 + threadIdx.x;
    if (e < N_EDGES) {
        float l = len[e];
        C[e] = (l <= 10.0f && l >= 0.0f) ? 1.0f : 0.0f;
    }
}

__global__ void zero_kernel(float4* __restrict__ p, int n4) {
    int i = blockIdx.x * 256 + threadIdx.x;
    if (i < n4) p[i] = make_float4(0.f, 0.f, 0.f, 0.f);
}

// ---------------- SGEMM: C[M,128] = A[M,K] @ B[K,128] (+epilogue) ----------------
// EPI 0: out = acc
// EPI 1: out = ssp(acc + bias[n])
// EPI 2: out = (acc + bias[n]) * aux[m]           (aux = per-row scale, the C mask)
// EPI 3: out = acc + bias[n] + aux[m*128+n]        (aux = residual addend)
#define BM 128
#define BN 128
#define BK 16

template<int EPI>
__global__ void __launch_bounds__(256) sgemm_kernel(
    const float* __restrict__ A, const float* __restrict__ B,
    const float* __restrict__ bias, const float* __restrict__ aux,
    float* __restrict__ out, int M, int K)
{
    __shared__ float As[BK][BM];
    __shared__ float Bs[BK][BN];
    const int tid = threadIdx.x;
    const int mBase = blockIdx.y * BM;
    const int tr = tid >> 4;        // 0..15 (row group)
    const int tc = tid & 15;        // 0..15 (col group)

    // A tile load mapping: 128 rows x 16 k, float4 along K (K % 4 == 0 for all our K)
    const int aRow = tid >> 2;          // 0..63, second pass +64
    const int aCol = (tid & 3) * 4;     // 0,4,8,12
    // B tile load mapping: 16 k-rows x 128 cols
    const int bRow = tid >> 5;          // 0..7, second pass +8
    const int bCol = (tid & 31) * 4;

    float acc[8][8];
#pragma unroll
    for (int i = 0; i < 8; i++)
#pragma unroll
        for (int j = 0; j < 8; j++) acc[i][j] = 0.0f;

    for (int k0 = 0; k0 < K; k0 += BK) {
#pragma unroll
        for (int p = 0; p < 2; p++) {
            int r = aRow + p * 64;
            int gm = mBase + r;
            int gk = k0 + aCol;
            float4 v = make_float4(0.f, 0.f, 0.f, 0.f);
            if (gm < M && gk < K)
                v = *reinterpret_cast<const float4*>(A + (size_t)gm * K + gk);
            As[aCol + 0][r] = v.x; As[aCol + 1][r] = v.y;
            As[aCol + 2][r] = v.z; As[aCol + 3][r] = v.w;
        }
#pragma unroll
        for (int p = 0; p < 2; p++) {
            int kr = bRow + p * 8;
            int gk = k0 + kr;
            float4 v = make_float4(0.f, 0.f, 0.f, 0.f);
            if (gk < K)
                v = *reinterpret_cast<const float4*>(B + (size_t)gk * BN + bCol);
            *reinterpret_cast<float4*>(&Bs[kr][bCol]) = v;
        }
        __syncthreads();
#pragma unroll
        for (int kk = 0; kk < BK; kk++) {
            float a[8], b[8];
#pragma unroll
            for (int i = 0; i < 8; i++) a[i] = As[kk][tr * 8 + i];
#pragma unroll
            for (int j = 0; j < 8; j++) b[j] = Bs[kk][tc * 8 + j];
#pragma unroll
            for (int i = 0; i < 8; i++)
#pragma unroll
                for (int j = 0; j < 8; j++)
                    acc[i][j] = fmaf(a[i], b[j], acc[i][j]);
        }
        __syncthreads();
    }

    float bn[8];
    if (EPI >= 1) {
#pragma unroll
        for (int j = 0; j < 8; j++) bn[j] = bias[tc * 8 + j];
    }

#pragma unroll
    for (int i = 0; i < 8; i++) {
        int gm = mBase + tr * 8 + i;
        if (gm < M) {
            float scale = 1.0f;
            if (EPI == 2) scale = aux[gm];
            float* orow = out + (size_t)gm * BN;
            const float* arow = (EPI == 3) ? (aux + (size_t)gm * BN) : nullptr;
#pragma unroll
            for (int j = 0; j < 8; j++) {
                int gn = tc * 8 + j;
                float v = acc[i][j];
                if (EPI >= 1) v += bn[j];
                if (EPI == 1) v = sspf(v);
                if (EPI == 2) v *= scale;
                if (EPI == 3) v += arow[gn];
                orow[gn] = v;
            }
        }
    }
}

// ---------------- scatter: agg[dst] += x[src] * W  (one warp per edge) ----------------
__global__ void __launch_bounds__(256) scatter_kernel(
    const float* __restrict__ x, const float* __restrict__ W,
    const float* __restrict__ C,
    const int* __restrict__ src, const int* __restrict__ dst,
    float* __restrict__ agg)
{
    int e = blockIdx.x * 8 + (threadIdx.x >> 5);
    if (e >= N_EDGES) return;
    if (C[e] == 0.0f) return;   // warp-uniform skip
    int lane = threadIdx.x & 31;
    int s = src[e], d = dst[e];
    float4 xv = reinterpret_cast<const float4*>(x + (size_t)s * HID)[lane];
    float4 wv = reinterpret_cast<const float4*>(W + (size_t)e * HID)[lane];
    float* ap = agg + (size_t)d * HID + lane * 4;
    atomicAdd(ap + 0, xv.x * wv.x);
    atomicAdd(ap + 1, xv.y * wv.y);
    atomicAdd(ap + 2, xv.z * wv.z);
    atomicAdd(ap + 3, xv.w * wv.w);
}

// ---------------- host launch ----------------
extern "C" void kernel_launch(void* const* d_in, const int* in_sizes, int n_in,
                              void* d_out, int out_size) {
    const float* z      = (const float*)d_in[0];
    const int*   ei     = (const int*)  d_in[1];
    const float* elen   = (const float*)d_in[2];
    const float* eattr  = (const float*)d_in[3];
    const float* emb_w  = (const float*)d_in[4];
    const float* emb_b  = (const float*)d_in[5];
    const float* lin1_w = (const float*)d_in[6];
    const float* nn_w1  = (const float*)d_in[7];
    const float* nn_b1  = (const float*)d_in[8];
    const float* nn_w2  = (const float*)d_in[9];
    const float* nn_b2  = (const float*)d_in[10];
    const float* lin2_w = (const float*)d_in[11];
    const float* lin2_b = (const float*)d_in[12];
    const float* lin_w  = (const float*)d_in[13];
    const float* lin_b  = (const float*)d_in[14];
    float* h = (float*)d_out;

    float *px, *pagg, *pT, *pW, *pC;
    cudaGetSymbolAddress((void**)&px,   g_x);
    cudaGetSymbolAddress((void**)&pagg, g_agg);
    cudaGetSymbolAddress((void**)&pT,   g_T);
    cudaGetSymbolAddress((void**)&pW,   g_W);
    cudaGetSymbolAddress((void**)&pC,   g_C);

    const int* src = ei;
    const int* dst = ei + N_EDGES;

    embed_kernel<<<N_NODES, HID>>>(z, emb_w, emb_b, h);
    cmask_kernel<<<(N_EDGES + 255) / 256, 256>>>(elen, pC);

    dim3 gNode(1, (N_NODES + BM - 1) / BM);   // 391
    dim3 gEdge(1, N_EDGES / BM);              // 6250
    const int aggN4 = N_NODES * HID / 4;

    for (int i = 0; i < N_BLOCKS; i++) {
        // x = h @ lin1_w[i]                 (no bias)
        sgemm_kernel<0><<<gNode, 256>>>(h, lin1_w + (size_t)i * HID * HID,
                                        nullptr, nullptr, px, N_NODES, HID);
        // T = ssp(edge_attr @ nn_w1[i] + nn_b1[i])
        sgemm_kernel<1><<<gEdge, 256>>>(eattr, nn_w1 + (size_t)i * EC * HID,
                                        nn_b1 + (size_t)i * HID, nullptr, pT, N_EDGES, EC);
        // W = (T @ nn_w2[i] + nn_b2[i]) * C
        sgemm_kernel<2><<<gEdge, 256>>>(pT, nn_w2 + (size_t)i * HID * HID,
                                        nn_b2 + (size_t)i * HID, pC, pW, N_EDGES, HID);
        // agg = 0 ; agg[dst] += x[src] * W
        zero_kernel<<<(aggN4 + 255) / 256, 256>>>((float4*)pagg, aggN4);
        scatter_kernel<<<(N_EDGES + 7) / 8, 256>>>(px, pW, pC, src, dst, pagg);
        // x = ssp(agg @ lin2_w[i] + lin2_b[i])
        sgemm_kernel<1><<<gNode, 256>>>(pagg, lin2_w + (size_t)i * HID * HID,
                                        lin2_b + (size_t)i * HID, nullptr, px, N_NODES, HID);
        // h = h + x @ lin_w[i] + lin_b[i]
        sgemm_kernel<3><<<gNode, 256>>>(px, lin_w + (size_t)i * HID * HID,
                                        lin_b + (size_t)i * HID, h, h, N_NODES, HID);
    }
}

// round 3
// speedup vs baseline: 1.4421x; 1.4421x over previous
#include <cuda_runtime.h>
#include <cstdint>
#include <math.h>

#define N_NODES 50000
#define N_EDGES 800000
#define HID 128
#define EC 100
#define IN_DIM 5
#define N_BLOCKS 6

// ---------------- scratch (device globals; no runtime allocation) ----------------
__device__ float g_x[N_NODES * HID];
__device__ float g_agg[N_NODES * HID];
__device__ float g_T[(size_t)N_EDGES * HID];
__device__ float g_W[(size_t)N_EDGES * HID];
__device__ float g_C[N_EDGES];

__device__ __forceinline__ float sspf(float x) {
    float sp = fmaxf(x, 0.0f) + log1pf(expf(-fabsf(x)));
    return sp - 0.69314718055994531f;
}

__device__ __forceinline__ uint32_t f2tf32(float f) {
    uint32_t r;
    asm("cvt.rna.tf32.f32 %0, %1;" : "=r"(r) : "f"(f));
    return r;
}

// ---------------- tf32 warp-MMA GEMM: out[M,128] = A[M,K] @ B[K,128] (+epilogue) ----
// mma.sync.m16n8k8.tf32 (portable sm_80+ path -> HMMA tensor pipe)
// Tiling: CTA 128x128xBK32, 8 warps in 2(M) x 4(N), warp tile 64x32,
//         warp = 4x4 grid of 16x8 mma tiles, 4 k-steps of 8 per chunk.
// EPI 0: out = acc
// EPI 1: out = ssp(acc + bias[n])
// EPI 2: out = (acc + bias[n]) * aux[m]
// EPI 3: out = acc + bias[n] + aux[m*128+n]
#define BK 32
#define AS_STRIDE 36   // pad: lds addr = row*36 + k -> banks 4g+t distinct
#define BS_STRIDE 132  // pad: lds addr = k*132 + n  -> banks 4t+g distinct

template<int EPI>
__global__ void __launch_bounds__(256) mma_gemm(
    const float* __restrict__ A, const float* __restrict__ B,
    const float* __restrict__ bias, const float* __restrict__ aux,
    float* __restrict__ out, int M, int K)
{
    __shared__ uint32_t As[128 * AS_STRIDE];  // [row][k] tf32
    __shared__ uint32_t Bs[BK * BS_STRIDE];   // [k][n]   tf32

    const int tid = threadIdx.x;
    const int wid = tid >> 5;
    const int lane = tid & 31;
    const int g = lane >> 2;      // groupID   0..7
    const int t = lane & 3;       // tid-in-group 0..3
    const int warpM = (wid & 1) * 64;
    const int warpN = (wid >> 1) * 32;
    const int mBase = blockIdx.x * 128;

    float c[4][4][4];
#pragma unroll
    for (int i = 0; i < 4; i++)
#pragma unroll
        for (int j = 0; j < 4; j++)
#pragma unroll
            for (int v = 0; v < 4; v++) c[i][j][v] = 0.0f;

    const int nChunks = (K + BK - 1) / BK;
    for (int ch = 0; ch < nChunks; ch++) {
        const int k0 = ch * BK;
        // load A tile: 128 rows x 32 k = 1024 float4, 4 per thread
#pragma unroll
        for (int i = 0; i < 4; i++) {
            int q = tid + (i << 8);
            int row = q >> 3, kq = (q & 7) << 2;
            int gm = mBase + row, gk = k0 + kq;
            float4 v = make_float4(0.f, 0.f, 0.f, 0.f);
            if (gm < M && gk < K)
                v = *reinterpret_cast<const float4*>(A + (size_t)gm * K + gk);
            uint32_t* p = As + row * AS_STRIDE + kq;
            p[0] = f2tf32(v.x); p[1] = f2tf32(v.y);
            p[2] = f2tf32(v.z); p[3] = f2tf32(v.w);
        }
        // load B tile: 32 k-rows x 128 n = 1024 float4, 4 per thread
#pragma unroll
        for (int i = 0; i < 4; i++) {
            int q = tid + (i << 8);
            int kr = q >> 5, nq = (q & 31) << 2;
            int gk = k0 + kr;
            float4 v = make_float4(0.f, 0.f, 0.f, 0.f);
            if (gk < K)
                v = *reinterpret_cast<const float4*>(B + (size_t)gk * 128 + nq);
            uint32_t* p = Bs + kr * BS_STRIDE + nq;
            p[0] = f2tf32(v.x); p[1] = f2tf32(v.y);
            p[2] = f2tf32(v.z); p[3] = f2tf32(v.w);
        }
        __syncthreads();

#pragma unroll
        for (int kk = 0; kk < 4; kk++) {
            const int kb = kk * 8;
            uint32_t a[4][4], b[4][2];
#pragma unroll
            for (int i = 0; i < 4; i++) {
                const uint32_t* ar = As + (warpM + i * 16 + g) * AS_STRIDE + kb + t;
                a[i][0] = ar[0];
                a[i][2] = ar[4];
                const uint32_t* ar8 = ar + 8 * AS_STRIDE;
                a[i][1] = ar8[0];
                a[i][3] = ar8[4];
            }
#pragma unroll
            for (int j = 0; j < 4; j++) {
                const uint32_t* br = Bs + (kb + t) * BS_STRIDE + warpN + j * 8 + g;
                b[j][0] = br[0];
                b[j][1] = br[4 * BS_STRIDE];
            }
#pragma unroll
            for (int i = 0; i < 4; i++)
#pragma unroll
                for (int j = 0; j < 4; j++) {
                    asm volatile(
                        "mma.sync.aligned.m16n8k8.row.col.f32.tf32.tf32.f32 "
                        "{%0,%1,%2,%3}, {%4,%5,%6,%7}, {%8,%9}, {%0,%1,%2,%3};\n"
                        : "+f"(c[i][j][0]), "+f"(c[i][j][1]), "+f"(c[i][j][2]), "+f"(c[i][j][3])
                        : "r"(a[i][0]), "r"(a[i][1]), "r"(a[i][2]), "r"(a[i][3]),
                          "r"(b[j][0]), "r"(b[j][1]));
                }
        }
        __syncthreads();
    }

    // epilogue: c[i][j]: rows (warpM+i*16+g, +8), cols (warpN+j*8+t*2, +1)
#pragma unroll
    for (int i = 0; i < 4; i++) {
#pragma unroll
        for (int half = 0; half < 2; half++) {
            const int r = warpM + i * 16 + g + half * 8;
            const int gm = mBase + r;
            if (gm < M) {
                float scale = (EPI == 2) ? __ldg(aux + gm) : 1.0f;
                float* orow = out + (size_t)gm * 128;
                const float* arow = (EPI == 3) ? (aux + (size_t)gm * 128) : nullptr;
#pragma unroll
                for (int j = 0; j < 4; j++) {
                    const int col = warpN + j * 8 + t * 2;
                    float v0 = c[i][j][half * 2 + 0];
                    float v1 = c[i][j][half * 2 + 1];
                    if (EPI >= 1) {
                        v0 += __ldg(bias + col);
                        v1 += __ldg(bias + col + 1);
                    }
                    if (EPI == 1) { v0 = sspf(v0); v1 = sspf(v1); }
                    if (EPI == 2) { v0 *= scale; v1 *= scale; }
                    if (EPI == 3) { v0 += arow[col]; v1 += arow[col + 1]; }
                    *reinterpret_cast<float2*>(orow + col) = make_float2(v0, v1);
                }
            }
        }
    }
}

// ---------------- small kernels ----------------
__global__ void embed_kernel(const float* __restrict__ z, const float* __restrict__ w,
                             const float* __restrict__ b, float* __restrict__ h) {
    int n = blockIdx.x, j = threadIdx.x;
    const float* zr = z + (size_t)n * (IN_DIM + HID);
    float acc = b[j] + zr[IN_DIM + j];
#pragma unroll
    for (int k = 0; k < IN_DIM; k++) acc = fmaf(zr[k], w[k * HID + j], acc);
    h[(size_t)n * HID + j] = acc;
}

__global__ void cmask_kernel(const float* __restrict__ len, float* __restrict__ C) {
    int e = blockIdx.x * 256 + threadIdx.x;
    if (e < N_EDGES) {
        float l = len[e];
        C[e] = (l <= 10.0f && l >= 0.0f) ? 1.0f : 0.0f;
    }
}

__global__ void zero_kernel(float4* __restrict__ p, int n4) {
    int i = blockIdx.x * 256 + threadIdx.x;
    if (i < n4) p[i] = make_float4(0.f, 0.f, 0.f, 0.f);
}

// ---------------- scatter: agg[dst] += x[src] * W  (one warp per edge) -----------
__global__ void __launch_bounds__(256) scatter_kernel(
    const float* __restrict__ x, const float* __restrict__ W,
    const float* __restrict__ C,
    const int* __restrict__ src, const int* __restrict__ dst,
    float* __restrict__ agg)
{
    int e = blockIdx.x * 8 + (threadIdx.x >> 5);
    if (e >= N_EDGES) return;
    if (C[e] == 0.0f) return;
    int lane = threadIdx.x & 31;
    int s = src[e], d = dst[e];
    float4 xv = reinterpret_cast<const float4*>(x + (size_t)s * HID)[lane];
    float4 wv = reinterpret_cast<const float4*>(W + (size_t)e * HID)[lane];
    float* ap = agg + (size_t)d * HID + lane * 4;
    atomicAdd(ap + 0, xv.x * wv.x);
    atomicAdd(ap + 1, xv.y * wv.y);
    atomicAdd(ap + 2, xv.z * wv.z);
    atomicAdd(ap + 3, xv.w * wv.w);
}

// ---------------- host launch ----------------
extern "C" void kernel_launch(void* const* d_in, const int* in_sizes, int n_in,
                              void* d_out, int out_size) {
    const float* z      = (const float*)d_in[0];
    const int*   ei     = (const int*)  d_in[1];
    const float* elen   = (const float*)d_in[2];
    const float* eattr  = (const float*)d_in[3];
    const float* emb_w  = (const float*)d_in[4];
    const float* emb_b  = (const float*)d_in[5];
    const float* lin1_w = (const float*)d_in[6];
    const float* nn_w1  = (const float*)d_in[7];
    const float* nn_b1  = (const float*)d_in[8];
    const float* nn_w2  = (const float*)d_in[9];
    const float* nn_b2  = (const float*)d_in[10];
    const float* lin2_w = (const float*)d_in[11];
    const float* lin2_b = (const float*)d_in[12];
    const float* lin_w  = (const float*)d_in[13];
    const float* lin_b  = (const float*)d_in[14];
    float* h = (float*)d_out;

    float *px, *pagg, *pT, *pW, *pC;
    cudaGetSymbolAddress((void**)&px,   g_x);
    cudaGetSymbolAddress((void**)&pagg, g_agg);
    cudaGetSymbolAddress((void**)&pT,   g_T);
    cudaGetSymbolAddress((void**)&pW,   g_W);
    cudaGetSymbolAddress((void**)&pC,   g_C);

    const int* src = ei;
    const int* dst = ei + N_EDGES;

    embed_kernel<<<N_NODES, HID>>>(z, emb_w, emb_b, h);
    cmask_kernel<<<(N_EDGES + 255) / 256, 256>>>(elen, pC);

    const int nodeTiles = (N_NODES + 127) / 128;   // 391
    const int edgeTiles = N_EDGES / 128;           // 6250
    const int aggN4 = N_NODES * HID / 4;

    for (int i = 0; i < N_BLOCKS; i++) {
        // x = h @ lin1_w[i]
        mma_gemm<0><<<nodeTiles, 256>>>(h, lin1_w + (size_t)i * HID * HID,
                                        nullptr, nullptr, px, N_NODES, HID);
        // T = ssp(edge_attr @ nn_w1[i] + nn_b1[i])
        mma_gemm<1><<<edgeTiles, 256>>>(eattr, nn_w1 + (size_t)i * EC * HID,
                                        nn_b1 + (size_t)i * HID, nullptr, pT, N_EDGES, EC);
        // W = (T @ nn_w2[i] + nn_b2[i]) * C
        mma_gemm<2><<<edgeTiles, 256>>>(pT, nn_w2 + (size_t)i * HID * HID,
                                        nn_b2 + (size_t)i * HID, pC, pW, N_EDGES, HID);
        // agg = 0 ; agg[dst] += x[src] * W
        zero_kernel<<<(aggN4 + 255) / 256, 256>>>((float4*)pagg, aggN4);
        scatter_kernel<<<(N_EDGES + 7) / 8, 256>>>(px, pW, pC, src, dst, pagg);
        // x = ssp(agg @ lin2_w[i] + lin2_b[i])
        mma_gemm<1><<<nodeTiles, 256>>>(pagg, lin2_w + (size_t)i * HID * HID,
                                        lin2_b + (size_t)i * HID, nullptr, px, N_NODES, HID);
        // h = h + x @ lin_w[i] + lin_b[i]
        mma_gemm<3><<<nodeTiles, 256>>>(px, lin_w + (size_t)i * HID * HID,
                                        lin_b + (size_t)i * HID, h, h, N_NODES, HID);
    }
}

// round 4
// speedup vs baseline: 1.8070x; 1.2530x over previous
#include <cuda_runtime.h>
#include <cstdint>
#include <math.h>

#define N_NODES 50000
#define N_EDGES 800000
#define HID 128
#define EC 100
#define IN_DIM 5
#define N_BLOCKS 6

// ---------------- scratch (device globals; no runtime allocation) ----------------
__device__ float g_x[N_NODES * HID];
__device__ float g_agg[N_NODES * HID];
__device__ float g_W[(size_t)N_EDGES * HID];
__device__ float g_C[N_EDGES];

__device__ __forceinline__ float sspf(float x) {
    float sp = fmaxf(x, 0.0f) + log1pf(expf(-fabsf(x)));
    return sp - 0.69314718055994531f;
}

__device__ __forceinline__ uint32_t f2tf32(float f) {
    uint32_t r;
    asm("cvt.rna.tf32.f32 %0, %1;" : "=r"(r) : "f"(f));
    return r;
}

// ---------------- shared tiling constants ----------------
#define AS_STRIDE 36    // A tile [128 rows][32 k], banks (4g+t) conflict-free
#define BS_STRIDE 132   // B tile [32 k][128 n],  banks (4t+g) conflict-free
#define T_STRIDE  132   // resident T tile [128 rows][128 k]
#define TWORDS (128 * T_STRIDE)
#define AWORDS (128 * AS_STRIDE)
#define BWORDS (32 * BS_STRIDE)
#define FUSED_SMEM ((TWORDS + 2 * AWORDS + 2 * BWORDS) * 4)
#define PLAIN_SMEM ((2 * AWORDS + 2 * BWORDS) * 4)

// ---------------- fragment helpers ----------------
// one 32-k chunk of mma compute: c += A(128x32) @ B(32x128), warp tile 64x32
template<int ASTR>
__device__ __forceinline__ void mma_chunk(const uint32_t* __restrict__ As,
                                          const uint32_t* __restrict__ Bs,
                                          float c[4][4][4],
                                          int warpM, int warpN, int g, int t)
{
#pragma unroll
    for (int kk = 0; kk < 4; kk++) {
        const int kb = kk * 8;
        uint32_t a[4][4], b[4][2];
#pragma unroll
        for (int i = 0; i < 4; i++) {
            const uint32_t* ar = As + (warpM + i * 16 + g) * ASTR + kb + t;
            a[i][0] = ar[0];
            a[i][2] = ar[4];
            const uint32_t* ar8 = ar + 8 * ASTR;
            a[i][1] = ar8[0];
            a[i][3] = ar8[4];
        }
#pragma unroll
        for (int j = 0; j < 4; j++) {
            const uint32_t* br = Bs + (kb + t) * BS_STRIDE + warpN + j * 8 + g;
            b[j][0] = br[0];
            b[j][1] = br[4 * BS_STRIDE];
        }
#pragma unroll
        for (int i = 0; i < 4; i++)
#pragma unroll
            for (int j = 0; j < 4; j++) {
                asm volatile(
                    "mma.sync.aligned.m16n8k8.row.col.f32.tf32.tf32.f32 "
                    "{%0,%1,%2,%3}, {%4,%5,%6,%7}, {%8,%9}, {%0,%1,%2,%3};\n"
                    : "+f"(c[i][j][0]), "+f"(c[i][j][1]), "+f"(c[i][j][2]), "+f"(c[i][j][3])
                    : "r"(a[i][0]), "r"(a[i][1]), "r"(a[i][2]), "r"(a[i][3]),
                      "r"(b[j][0]), "r"(b[j][1]));
            }
    }
}

__device__ __forceinline__ void loadA_g(float4* r, const float* __restrict__ A,
                                        int mBase, int k0, int M, int K, int tid) {
#pragma unroll
    for (int i = 0; i < 4; i++) {
        int q = tid + (i << 8);
        int row = q >> 3, kq = (q & 7) << 2;
        int gm = mBase + row, gk = k0 + kq;
        r[i] = make_float4(0.f, 0.f, 0.f, 0.f);
        if (gm < M && gk < K)
            r[i] = *reinterpret_cast<const float4*>(A + (size_t)gm * K + gk);
    }
}
__device__ __forceinline__ void storeA_s(uint32_t* __restrict__ buf, const float4* r, int tid) {
#pragma unroll
    for (int i = 0; i < 4; i++) {
        int q = tid + (i << 8);
        int row = q >> 3, kq = (q & 7) << 2;
        uint32_t* p = buf + row * AS_STRIDE + kq;
        p[0] = f2tf32(r[i].x); p[1] = f2tf32(r[i].y);
        p[2] = f2tf32(r[i].z); p[3] = f2tf32(r[i].w);
    }
}
__device__ __forceinline__ void loadB_g(float4* r, const float* __restrict__ B,
                                        int k0, int K, int tid) {
#pragma unroll
    for (int i = 0; i < 4; i++) {
        int q = tid + (i << 8);
        int kr = q >> 5, nq = (q & 31) << 2;
        int gk = k0 + kr;
        r[i] = make_float4(0.f, 0.f, 0.f, 0.f);
        if (gk < K)
            r[i] = *reinterpret_cast<const float4*>(B + (size_t)gk * 128 + nq);
    }
}
__device__ __forceinline__ void storeB_s(uint32_t* __restrict__ buf, const float4* r, int tid) {
#pragma unroll
    for (int i = 0; i < 4; i++) {
        int q = tid + (i << 8);
        int kr = q >> 5, nq = (q & 31) << 2;
        uint32_t* p = buf + kr * BS_STRIDE + nq;
        p[0] = f2tf32(r[i].x); p[1] = f2tf32(r[i].y);
        p[2] = f2tf32(r[i].z); p[3] = f2tf32(r[i].w);
    }
}

// ---------------- fused double GEMM ----------------
// stage1: T = ssp(A[M,K1] @ B1[K1,128] + b1)   (kept in smem, tf32)
// stage2: out = epilogue(T @ B2[128,128] + b2)
//   EPI2==2: out = (acc + b2[n]) * aux[m]                 (edge path: *C mask)
//   EPI2==3: out = acc + b2[n] + aux[m*128+n]             (node path: +h residual)
template<int EPI2>
__global__ void __launch_bounds__(256, 1) fused2_gemm(
    const float* __restrict__ A, const float* __restrict__ B1, const float* __restrict__ b1,
    const float* __restrict__ B2, const float* __restrict__ b2,
    const float* __restrict__ aux, float* __restrict__ out, int M, int K1)
{
    extern __shared__ uint32_t sm[];
    uint32_t* Tt = sm;
    uint32_t* As0 = sm + TWORDS;
    uint32_t* As1 = As0 + AWORDS;
    uint32_t* Bs0 = As1 + AWORDS;
    uint32_t* Bs1 = Bs0 + BWORDS;

    const int tid = threadIdx.x;
    const int wid = tid >> 5, lane = tid & 31;
    const int g = lane >> 2, t = lane & 3;
    const int warpM = (wid & 1) * 64, warpN = (wid >> 1) * 32;
    const int mBase = blockIdx.x * 128;

    float c[4][4][4];
#pragma unroll
    for (int i = 0; i < 4; i++)
#pragma unroll
        for (int j = 0; j < 4; j++)
#pragma unroll
            for (int v = 0; v < 4; v++) c[i][j][v] = 0.0f;

    float4 aR[4], bR[4];
    const int nCh = (K1 + 31) >> 5;

    // ---- stage 1: double-buffered over K1 ----
    loadA_g(aR, A, mBase, 0, M, K1, tid);
    loadB_g(bR, B1, 0, K1, tid);
    storeA_s(As0, aR, tid);
    storeB_s(Bs0, bR, tid);
    __syncthreads();
    for (int ch = 0; ch < nCh; ch++) {
        if (ch + 1 < nCh) {
            loadA_g(aR, A, mBase, (ch + 1) * 32, M, K1, tid);
            loadB_g(bR, B1, (ch + 1) * 32, K1, tid);
        }
        mma_chunk<AS_STRIDE>((ch & 1) ? As1 : As0, (ch & 1) ? Bs1 : Bs0, c, warpM, warpN, g, t);
        if (ch + 1 < nCh) {
            storeA_s(((ch + 1) & 1) ? As1 : As0, aR, tid);
            storeB_s(((ch + 1) & 1) ? Bs1 : Bs0, bR, tid);
        }
        __syncthreads();
    }

    // ---- stage1 epilogue: ssp(c + b1) -> T tile (tf32, K-major) ----
#pragma unroll
    for (int i = 0; i < 4; i++)
#pragma unroll
        for (int half = 0; half < 2; half++) {
            const int r = warpM + i * 16 + g + half * 8;
#pragma unroll
            for (int j = 0; j < 4; j++) {
                const int col = warpN + j * 8 + t * 2;
                float v0 = sspf(c[i][j][half * 2 + 0] + __ldg(b1 + col));
                float v1 = sspf(c[i][j][half * 2 + 1] + __ldg(b1 + col + 1));
                uint32_t* p = Tt + r * T_STRIDE + col;
                p[0] = f2tf32(v0);
                p[1] = f2tf32(v1);
            }
        }
#pragma unroll
    for (int i = 0; i < 4; i++)
#pragma unroll
        for (int j = 0; j < 4; j++)
#pragma unroll
            for (int v = 0; v < 4; v++) c[i][j][v] = 0.0f;

    // ---- stage 2: T (resident) @ B2, double-buffered B ----
    loadB_g(bR, B2, 0, 128, tid);   // reg prefetch before barrier
    __syncthreads();                // T visible to all warps, Bs buffers free
    storeB_s(Bs0, bR, tid);
    __syncthreads();
    for (int ch = 0; ch < 4; ch++) {
        if (ch < 3) loadB_g(bR, B2, (ch + 1) * 32, 128, tid);
        mma_chunk<T_STRIDE>(Tt + ch * 32, (ch & 1) ? Bs1 : Bs0, c, warpM, warpN, g, t);
        if (ch < 3) storeB_s(((ch + 1) & 1) ? Bs1 : Bs0, bR, tid);
        __syncthreads();
    }

    // ---- final epilogue ----
#pragma unroll
    for (int i = 0; i < 4; i++)
#pragma unroll
        for (int half = 0; half < 2; half++) {
            const int r = warpM + i * 16 + g + half * 8;
            const int gm = mBase + r;
            if (gm < M) {
                float scale = (EPI2 == 2) ? __ldg(aux + gm) : 1.0f;
                float* orow = out + (size_t)gm * 128;
                const float* arow = (EPI2 == 3) ? (aux + (size_t)gm * 128) : nullptr;
#pragma unroll
                for (int j = 0; j < 4; j++) {
                    const int col = warpN + j * 8 + t * 2;
                    float v0 = c[i][j][half * 2 + 0] + __ldg(b2 + col);
                    float v1 = c[i][j][half * 2 + 1] + __ldg(b2 + col + 1);
                    if (EPI2 == 2) { v0 *= scale; v1 *= scale; }
                    if (EPI2 == 3) { v0 += arow[col]; v1 += arow[col + 1]; }
                    *reinterpret_cast<float2*>(orow + col) = make_float2(v0, v1);
                }
            }
        }
}

// ---------------- plain GEMM (lin1): out[M,128] = A[M,128] @ B[128,128] ----------
__global__ void __launch_bounds__(256, 1) gemm_plain(
    const float* __restrict__ A, const float* __restrict__ B,
    float* __restrict__ out, int M)
{
    extern __shared__ uint32_t sm[];
    uint32_t* As0 = sm;
    uint32_t* As1 = As0 + AWORDS;
    uint32_t* Bs0 = As1 + AWORDS;
    uint32_t* Bs1 = Bs0 + BWORDS;

    const int tid = threadIdx.x;
    const int wid = tid >> 5, lane = tid & 31;
    const int g = lane >> 2, t = lane & 3;
    const int warpM = (wid & 1) * 64, warpN = (wid >> 1) * 32;
    const int mBase = blockIdx.x * 128;

    float c[4][4][4];
#pragma unroll
    for (int i = 0; i < 4; i++)
#pragma unroll
        for (int j = 0; j < 4; j++)
#pragma unroll
            for (int v = 0; v < 4; v++) c[i][j][v] = 0.0f;

    float4 aR[4], bR[4];
    loadA_g(aR, A, mBase, 0, M, 128, tid);
    loadB_g(bR, B, 0, 128, tid);
    storeA_s(As0, aR, tid);
    storeB_s(Bs0, bR, tid);
    __syncthreads();
    for (int ch = 0; ch < 4; ch++) {
        if (ch < 3) {
            loadA_g(aR, A, mBase, (ch + 1) * 32, M, 128, tid);
            loadB_g(bR, B, (ch + 1) * 32, 128, tid);
        }
        mma_chunk<AS_STRIDE>((ch & 1) ? As1 : As0, (ch & 1) ? Bs1 : Bs0, c, warpM, warpN, g, t);
        if (ch < 3) {
            storeA_s(((ch + 1) & 1) ? As1 : As0, aR, tid);
            storeB_s(((ch + 1) & 1) ? Bs1 : Bs0, bR, tid);
        }
        __syncthreads();
    }
#pragma unroll
    for (int i = 0; i < 4; i++)
#pragma unroll
        for (int half = 0; half < 2; half++) {
            const int gm = mBase + warpM + i * 16 + g + half * 8;
            if (gm < M) {
                float* orow = out + (size_t)gm * 128;
#pragma unroll
                for (int j = 0; j < 4; j++) {
                    const int col = warpN + j * 8 + t * 2;
                    *reinterpret_cast<float2*>(orow + col) =
                        make_float2(c[i][j][half * 2 + 0], c[i][j][half * 2 + 1]);
                }
            }
        }
}

// ---------------- small kernels ----------------
__global__ void embed_kernel(const float* __restrict__ z, const float* __restrict__ w,
                             const float* __restrict__ b, float* __restrict__ h) {
    int n = blockIdx.x, j = threadIdx.x;
    const float* zr = z + (size_t)n * (IN_DIM + HID);
    float acc = b[j] + zr[IN_DIM + j];
#pragma unroll
    for (int k = 0; k < IN_DIM; k++) acc = fmaf(zr[k], w[k * HID + j], acc);
    h[(size_t)n * HID + j] = acc;
}

__global__ void cmask_kernel(const float* __restrict__ len, float* __restrict__ C) {
    int e = blockIdx.x * 256 + threadIdx.x;
    if (e < N_EDGES) {
        float l = len[e];
        C[e] = (l <= 10.0f && l >= 0.0f) ? 1.0f : 0.0f;
    }
}

__global__ void zero_kernel(float4* __restrict__ p, int n4) {
    int i = blockIdx.x * 256 + threadIdx.x;
    if (i < n4) p[i] = make_float4(0.f, 0.f, 0.f, 0.f);
}

// ---------------- scatter: agg[dst] += x[src] * W  (one warp per edge) -----------
__global__ void __launch_bounds__(256) scatter_kernel(
    const float* __restrict__ x, const float* __restrict__ W,
    const float* __restrict__ C,
    const int* __restrict__ src, const int* __restrict__ dst,
    float* __restrict__ agg)
{
    int e = blockIdx.x * 8 + (threadIdx.x >> 5);
    if (e >= N_EDGES) return;
    if (C[e] == 0.0f) return;
    int lane = threadIdx.x & 31;
    int s = src[e], d = dst[e];
    float4 xv = reinterpret_cast<const float4*>(x + (size_t)s * HID)[lane];
    float4 wv = reinterpret_cast<const float4*>(W + (size_t)e * HID)[lane];
    float* ap = agg + (size_t)d * HID + lane * 4;
    atomicAdd(ap + 0, xv.x * wv.x);
    atomicAdd(ap + 1, xv.y * wv.y);
    atomicAdd(ap + 2, xv.z * wv.z);
    atomicAdd(ap + 3, xv.w * wv.w);
}

// ---------------- host launch ----------------
extern "C" void kernel_launch(void* const* d_in, const int* in_sizes, int n_in,
                              void* d_out, int out_size) {
    const float* z      = (const float*)d_in[0];
    const int*   ei     = (const int*)  d_in[1];
    const float* elen   = (const float*)d_in[2];
    const float* eattr  = (const float*)d_in[3];
    const float* emb_w  = (const float*)d_in[4];
    const float* emb_b  = (const float*)d_in[5];
    const float* lin1_w = (const float*)d_in[6];
    const float* nn_w1  = (const float*)d_in[7];
    const float* nn_b1  = (const float*)d_in[8];
    const float* nn_w2  = (const float*)d_in[9];
    const float* nn_b2  = (const float*)d_in[10];
    const float* lin2_w = (const float*)d_in[11];
    const float* lin2_b = (const float*)d_in[12];
    const float* lin_w  = (const float*)d_in[13];
    const float* lin_b  = (const float*)d_in[14];
    float* h = (float*)d_out;

    float *px, *pagg, *pW, *pC;
    cudaGetSymbolAddress((void**)&px,   g_x);
    cudaGetSymbolAddress((void**)&pagg, g_agg);
    cudaGetSymbolAddress((void**)&pW,   g_W);
    cudaGetSymbolAddress((void**)&pC,   g_C);

    cudaFuncSetAttribute(fused2_gemm<2>, cudaFuncAttributeMaxDynamicSharedMemorySize, FUSED_SMEM);
    cudaFuncSetAttribute(fused2_gemm<3>, cudaFuncAttributeMaxDynamicSharedMemorySize, FUSED_SMEM);
    cudaFuncSetAttribute(gemm_plain,     cudaFuncAttributeMaxDynamicSharedMemorySize, PLAIN_SMEM);

    const int* src = ei;
    const int* dst = ei + N_EDGES;

    embed_kernel<<<N_NODES, HID>>>(z, emb_w, emb_b, h);
    cmask_kernel<<<(N_EDGES + 255) / 256, 256>>>(elen, pC);

    const int nodeTiles = (N_NODES + 127) / 128;   // 391
    const int edgeTiles = N_EDGES / 128;           // 6250
    const int aggN4 = N_NODES * HID / 4;

    for (int i = 0; i < N_BLOCKS; i++) {
        // x = h @ lin1_w[i]
        gemm_plain<<<nodeTiles, 256, PLAIN_SMEM>>>(h, lin1_w + (size_t)i * HID * HID, px, N_NODES);
        // W = (ssp(eattr @ nn_w1 + nn_b1) @ nn_w2 + nn_b2) * C   [fused]
        fused2_gemm<2><<<edgeTiles, 256, FUSED_SMEM>>>(
            eattr, nn_w1 + (size_t)i * EC * HID, nn_b1 + (size_t)i * HID,
            nn_w2 + (size_t)i * HID * HID, nn_b2 + (size_t)i * HID,
            pC, pW, N_EDGES, EC);
        // agg = 0 ; agg[dst] += x[src] * W
        zero_kernel<<<(aggN4 + 255) / 256, 256>>>((float4*)pagg, aggN4);
        scatter_kernel<<<(N_EDGES + 7) / 8, 256>>>(px, pW, pC, src, dst, pagg);
        // h = ssp(agg @ lin2 + b2) @ lin + b + h   [fused]
        fused2_gemm<3><<<nodeTiles, 256, FUSED_SMEM>>>(
            pagg, lin2_w + (size_t)i * HID * HID, lin2_b + (size_t)i * HID,
            lin_w + (size_t)i * HID * HID, lin_b + (size_t)i * HID,
            h, h, N_NODES, HID);
    }
}

// round 5
// speedup vs baseline: 1.8404x; 1.0185x over previous
#include <cuda_runtime.h>
#include <cstdint>
#include <math.h>

#define N_NODES 50000
#define N_EDGES 800000
#define HID 128
#define EC 100
#define IN_DIM 5
#define N_BLOCKS 6

// ---------------- scratch (device globals; no runtime allocation) ----------------
__device__ float g_x[N_NODES * HID];
__device__ float g_agg[N_NODES * HID];
__device__ float g_C[N_EDGES];

__device__ __forceinline__ float sspf(float x) {
    float sp = fmaxf(x, 0.0f) + log1pf(expf(-fabsf(x)));
    return sp - 0.69314718055994531f;
}

__device__ __forceinline__ uint32_t f2tf32(float f) {
    uint32_t r;
    asm("cvt.rna.tf32.f32 %0, %1;" : "=r"(r) : "f"(f));
    return r;
}

// ---------------- fragment-order smem layout (all strides in words) ----------------
// A-frag chunk: [i-tile 0..7][kt 0..3][lane 0..31][w 0..3]  (w = a0,a1,a2,a3)
// B-frag chunk: [pair 0..7][kt 0..3][lane 0..31][w 0..3]    (w = b0e,b1e,b0o,b1o)
// T-frag tile:  [i-tile 0..7][kt 0..15][lane][w]
#define AKT_STR 132
#define AI_STR  528       // 4 * AKT_STR
#define AWORDS  4224      // 8 * AI_STR
#define BKT_STR 132
#define BP_STR  528
#define BWORDS  4224
#define TI_STR  2112      // 16 * AKT_STR
#define TWORDS  16896     // 8 * TI_STR

#define FUSED_SMEM ((TWORDS + 2 * AWORDS + 2 * BWORDS) * 4)
#define PLAIN_SMEM ((2 * AWORDS + 2 * BWORDS) * 4)

// ---------------- global->reg loaders ----------------
__device__ __forceinline__ void loadA_g(float4* r, const float* __restrict__ A,
                                        int mBase, int k0, int M, int K, int tid) {
#pragma unroll
    for (int i = 0; i < 4; i++) {
        int q = tid + (i << 8);
        int row = q >> 3, kq = (q & 7) << 2;
        int gm = mBase + row, gk = k0 + kq;
        r[i] = make_float4(0.f, 0.f, 0.f, 0.f);
        if (gm < M && gk < K)
            r[i] = *reinterpret_cast<const float4*>(A + (size_t)gm * K + gk);
    }
}
__device__ __forceinline__ void loadB_g(float4* r, const float* __restrict__ B,
                                        int k0, int K, int tid) {
#pragma unroll
    for (int i = 0; i < 4; i++) {
        int q = tid + (i << 8);
        int kr = q >> 5, nq = (q & 31) << 2;
        int gk = k0 + kr;
        r[i] = make_float4(0.f, 0.f, 0.f, 0.f);
        if (gk < K)
            r[i] = *reinterpret_cast<const float4*>(B + (size_t)gk * 128 + nq);
    }
}

// ---------------- reg->smem fragment-order stores ----------------
__device__ __forceinline__ void storeA_f(uint32_t* __restrict__ buf, const float4* r, int tid) {
#pragma unroll
    for (int i4 = 0; i4 < 4; i4++) {
        int q = tid + (i4 << 8);
        int row = q >> 3, kq = (q & 7) << 2;
        int iT = row >> 4, rl = row & 15;
        int g = rl & 7, half = rl >> 3;
        int kt = kq >> 3;
        int w = half + ((kq & 4) ? 2 : 0);
        uint32_t* p = buf + iT * AI_STR + kt * AKT_STR + g * 16 + w;
        p[0]  = f2tf32(r[i4].x);
        p[4]  = f2tf32(r[i4].y);
        p[8]  = f2tf32(r[i4].z);
        p[12] = f2tf32(r[i4].w);
    }
}
__device__ __forceinline__ void storeB_f(uint32_t* __restrict__ buf, const float4* r, int tid) {
#pragma unroll
    for (int i4 = 0; i4 < 4; i4++) {
        int q = tid + (i4 << 8);
        int kr = q >> 5, nq = (q & 31) << 2;
        int kt = kr >> 3, t = kr & 3;
        int bh = (kr & 4) ? 1 : 0;
        int ntile = nq >> 3, g0 = nq & 7;
        int pair = ntile >> 1;
        int w = ((ntile & 1) << 1) + bh;
        uint32_t* p = buf + pair * BP_STR + kt * BKT_STR + (g0 * 4 + t) * 4 + w;
        p[0]  = f2tf32(r[i4].x);
        p[16] = f2tf32(r[i4].y);
        p[32] = f2tf32(r[i4].z);
        p[48] = f2tf32(r[i4].w);
    }
}

// ---------------- one 32-k chunk of mma: c += A(128x32)@B(32x128) -----------------
template<int ISTR>
__device__ __forceinline__ void mma_chunk_f(const uint32_t* __restrict__ As,
                                            const uint32_t* __restrict__ Bs,
                                            float c[4][4][4], int wid, int lane)
{
    const uint32_t* Ab = As + ((wid & 1) * 4) * ISTR + lane * 4;
    const uint32_t* Bb = Bs + ((wid >> 1) * 2) * BP_STR + lane * 4;
#pragma unroll
    for (int kk = 0; kk < 4; kk++) {
        uint32_t a[4][4], b[4][2];
#pragma unroll
        for (int i = 0; i < 4; i++) {
            uint4 av = *reinterpret_cast<const uint4*>(Ab + i * ISTR + kk * AKT_STR);
            a[i][0] = av.x; a[i][1] = av.y; a[i][2] = av.z; a[i][3] = av.w;
        }
#pragma unroll
        for (int p = 0; p < 2; p++) {
            uint4 bv = *reinterpret_cast<const uint4*>(Bb + p * BP_STR + kk * BKT_STR);
            b[2 * p][0] = bv.x;     b[2 * p][1] = bv.y;
            b[2 * p + 1][0] = bv.z; b[2 * p + 1][1] = bv.w;
        }
#pragma unroll
        for (int i = 0; i < 4; i++)
#pragma unroll
            for (int j = 0; j < 4; j++) {
                asm volatile(
                    "mma.sync.aligned.m16n8k8.row.col.f32.tf32.tf32.f32 "
                    "{%0,%1,%2,%3}, {%4,%5,%6,%7}, {%8,%9}, {%0,%1,%2,%3};\n"
                    : "+f"(c[i][j][0]), "+f"(c[i][j][1]), "+f"(c[i][j][2]), "+f"(c[i][j][3])
                    : "r"(a[i][0]), "r"(a[i][1]), "r"(a[i][2]), "r"(a[i][3]),
                      "r"(b[j][0]), "r"(b[j][1]));
            }
    }
}

__device__ __forceinline__ void zero_c(float c[4][4][4]) {
#pragma unroll
    for (int i = 0; i < 4; i++)
#pragma unroll
        for (int j = 0; j < 4; j++)
#pragma unroll
            for (int v = 0; v < 4; v++) c[i][j][v] = 0.0f;
}

// store epilogue values (optionally ssp) into T fragment layout (resident A for stage2/3)
__device__ __forceinline__ void store_T_frag(uint32_t* __restrict__ Tt, const float c[4][4][4],
                                             const float* bn, int wid, int g, int t, bool doSsp)
{
    const int iTb = (wid & 1) * 4;
    const int ktb = (wid >> 1) * 4;
#pragma unroll
    for (int i = 0; i < 4; i++)
#pragma unroll
        for (int half = 0; half < 2; half++)
#pragma unroll
            for (int j = 0; j < 4; j++)
#pragma unroll
                for (int d = 0; d < 2; d++) {
                    float v = c[i][j][half * 2 + d] + bn[j * 2 + d];
                    if (doSsp) v = sspf(v);
                    int col7 = t * 2 + d;
                    int tp = col7 & 3, bh = col7 >> 2;
                    Tt[(iTb + i) * TI_STR + (ktb + j) * AKT_STR + (g * 4 + tp) * 4 + half + 2 * bh]
                        = f2tf32(v);
                }
}

// ---------------- fused edge kernel: GEMM+ssp+GEMM+mask + scatter -----------------
// T = ssp(eattr@B1 + b1); W = (T@B2 + b2)*C[e];  agg[dst[e]] += x[src[e]] * W[e]
__global__ void __launch_bounds__(256, 1) edge_fused(
    const float* __restrict__ eattr, const float* __restrict__ B1, const float* __restrict__ b1,
    const float* __restrict__ B2, const float* __restrict__ b2,
    const float* __restrict__ Cm, const int* __restrict__ src, const int* __restrict__ dst,
    const float* __restrict__ x, float* __restrict__ agg)
{
    extern __shared__ uint32_t sm[];
    uint32_t* Tt  = sm;
    uint32_t* As0 = sm + TWORDS;
    uint32_t* As1 = As0 + AWORDS;
    uint32_t* Bs0 = As1 + AWORDS;
    uint32_t* Bs1 = Bs0 + BWORDS;

    const int tid = threadIdx.x;
    const int wid = tid >> 5, lane = tid & 31;
    const int g = lane >> 2, t = lane & 3;
    const int warpM = (wid & 1) * 64, warpN = (wid >> 1) * 32;
    const int mBase = blockIdx.x * 128;

    float c[4][4][4];
    zero_c(c);
    float4 aR[4], bR[4];

    // stage 1 (K=EC=100 -> 4 chunks), double buffered
    loadA_g(aR, eattr, mBase, 0, N_EDGES, EC, tid);
    loadB_g(bR, B1, 0, EC, tid);
    storeA_f(As0, aR, tid);
    storeB_f(Bs0, bR, tid);
    __syncthreads();
    for (int ch = 0; ch < 4; ch++) {
        if (ch < 3) {
            loadA_g(aR, eattr, mBase, (ch + 1) * 32, N_EDGES, EC, tid);
            loadB_g(bR, B1, (ch + 1) * 32, EC, tid);
        }
        mma_chunk_f<AI_STR>((ch & 1) ? As1 : As0, (ch & 1) ? Bs1 : Bs0, c, wid, lane);
        if (ch < 3) {
            storeA_f(((ch + 1) & 1) ? As1 : As0, aR, tid);
            storeB_f(((ch + 1) & 1) ? Bs1 : Bs0, bR, tid);
        }
        __syncthreads();
    }

    float bn1[8];
#pragma unroll
    for (int j = 0; j < 4; j++) {
        bn1[j * 2 + 0] = __ldg(b1 + warpN + j * 8 + t * 2 + 0);
        bn1[j * 2 + 1] = __ldg(b1 + warpN + j * 8 + t * 2 + 1);
    }
    store_T_frag(Tt, c, bn1, wid, g, t, true);
    zero_c(c);

    // stage 2: T (resident) @ B2
    loadB_g(bR, B2, 0, 128, tid);
    __syncthreads();               // T visible; stage1 buffer reads done
    storeB_f(Bs0, bR, tid);
    __syncthreads();
    for (int ch = 0; ch < 4; ch++) {
        if (ch < 3) loadB_g(bR, B2, (ch + 1) * 32, 128, tid);
        mma_chunk_f<TI_STR>(Tt + ch * 4 * AKT_STR, (ch & 1) ? Bs1 : Bs0, c, wid, lane);
        if (ch < 3) storeB_f(((ch + 1) & 1) ? Bs1 : Bs0, bR, tid);
        __syncthreads();
    }

    // scatter epilogue: no W materialization
    float bn2[8];
#pragma unroll
    for (int j = 0; j < 4; j++) {
        bn2[j * 2 + 0] = __ldg(b2 + warpN + j * 8 + t * 2 + 0);
        bn2[j * 2 + 1] = __ldg(b2 + warpN + j * 8 + t * 2 + 1);
    }
#pragma unroll
    for (int i = 0; i < 4; i++)
#pragma unroll
        for (int half = 0; half < 2; half++) {
            const int e = mBase + warpM + i * 16 + g + half * 8;
            const float cmv = __ldg(Cm + e);
            if (cmv != 0.0f) {
                const int s = __ldg(src + e), d = __ldg(dst + e);
                const float* xr = x + (size_t)s * 128;
                float* ar = agg + (size_t)d * 128;
#pragma unroll
                for (int j = 0; j < 4; j++) {
                    const int col = warpN + j * 8 + t * 2;
                    float2 xv = *reinterpret_cast<const float2*>(xr + col);
                    float w0 = (c[i][j][half * 2 + 0] + bn2[j * 2 + 0]) * cmv;
                    float w1 = (c[i][j][half * 2 + 1] + bn2[j * 2 + 1]) * cmv;
                    float m0 = xv.x * w0, m1 = xv.y * w1;
                    asm volatile("red.global.add.v2.f32 [%0], {%1, %2};"
                                 :: "l"(ar + col), "f"(m0), "f"(m1) : "memory");
                }
            }
        }
}

// ---------------- fused node kernel ----------------
// hnew = ssp(agg@B1 + b1)@B2 + b2 + h;  h = hnew;  if lin1: xOut = hnew@lin1
__global__ void __launch_bounds__(256, 1) node_fused(
    const float* __restrict__ agg, const float* __restrict__ B1, const float* __restrict__ b1,
    const float* __restrict__ B2, const float* __restrict__ b2,
    float* __restrict__ h, const float* __restrict__ lin1, float* __restrict__ xOut)
{
    extern __shared__ uint32_t sm[];
    uint32_t* Tt  = sm;
    uint32_t* As0 = sm + TWORDS;
    uint32_t* As1 = As0 + AWORDS;
    uint32_t* Bs0 = As1 + AWORDS;
    uint32_t* Bs1 = Bs0 + BWORDS;

    const int tid = threadIdx.x;
    const int wid = tid >> 5, lane = tid & 31;
    const int g = lane >> 2, t = lane & 3;
    const int warpM = (wid & 1) * 64, warpN = (wid >> 1) * 32;
    const int mBase = blockIdx.x * 128;

    float c[4][4][4];
    zero_c(c);
    float4 aR[4], bR[4];

    // stage 1: agg @ B1 (K=128)
    loadA_g(aR, agg, mBase, 0, N_NODES, 128, tid);
    loadB_g(bR, B1, 0, 128, tid);
    storeA_f(As0, aR, tid);
    storeB_f(Bs0, bR, tid);
    __syncthreads();
    for (int ch = 0; ch < 4; ch++) {
        if (ch < 3) {
            loadA_g(aR, agg, mBase, (ch + 1) * 32, N_NODES, 128, tid);
            loadB_g(bR, B1, (ch + 1) * 32, 128, tid);
        }
        mma_chunk_f<AI_STR>((ch & 1) ? As1 : As0, (ch & 1) ? Bs1 : Bs0, c, wid, lane);
        if (ch < 3) {
            storeA_f(((ch + 1) & 1) ? As1 : As0, aR, tid);
            storeB_f(((ch + 1) & 1) ? Bs1 : Bs0, bR, tid);
        }
        __syncthreads();
    }

    float bn1[8];
#pragma unroll
    for (int j = 0; j < 4; j++) {
        bn1[j * 2 + 0] = __ldg(b1 + warpN + j * 8 + t * 2 + 0);
        bn1[j * 2 + 1] = __ldg(b1 + warpN + j * 8 + t * 2 + 1);
    }
    store_T_frag(Tt, c, bn1, wid, g, t, true);
    zero_c(c);

    // stage 2: T @ B2
    loadB_g(bR, B2, 0, 128, tid);
    __syncthreads();
    storeB_f(Bs0, bR, tid);
    __syncthreads();
    for (int ch = 0; ch < 4; ch++) {
        if (ch < 3) loadB_g(bR, B2, (ch + 1) * 32, 128, tid);
        mma_chunk_f<TI_STR>(Tt + ch * 4 * AKT_STR, (ch & 1) ? Bs1 : Bs0, c, wid, lane);
        if (ch < 3) storeB_f(((ch + 1) & 1) ? Bs1 : Bs0, bR, tid);
        __syncthreads();
    }

    // stage-2 epilogue: h += residual, write h, and keep hnew resident in T-frag
    float bn2[8];
#pragma unroll
    for (int j = 0; j < 4; j++) {
        bn2[j * 2 + 0] = __ldg(b2 + warpN + j * 8 + t * 2 + 0);
        bn2[j * 2 + 1] = __ldg(b2 + warpN + j * 8 + t * 2 + 1);
    }
    const int iTb = (wid & 1) * 4;
    const int ktb = (wid >> 1) * 4;
#pragma unroll
    for (int i = 0; i < 4; i++)
#pragma unroll
        for (int half = 0; half < 2; half++) {
            const int gm = mBase + warpM + i * 16 + g + half * 8;
            const bool ok = gm < N_NODES;
            float* hrow = h + (size_t)gm * 128;
#pragma unroll
            for (int j = 0; j < 4; j++) {
                const int col = warpN + j * 8 + t * 2;
                float v0 = c[i][j][half * 2 + 0] + bn2[j * 2 + 0];
                float v1 = c[i][j][half * 2 + 1] + bn2[j * 2 + 1];
                if (ok) {
                    float2 hv = *reinterpret_cast<const float2*>(hrow + col);
                    v0 += hv.x; v1 += hv.y;
                    *reinterpret_cast<float2*>(hrow + col) = make_float2(v0, v1);
                }
                // keep hnew resident for stage 3
#pragma unroll
                for (int d = 0; d < 2; d++) {
                    float v = d ? v1 : v0;
                    int col7 = t * 2 + d;
                    int tp = col7 & 3, bh = col7 >> 2;
                    Tt[(iTb + i) * TI_STR + (ktb + j) * AKT_STR + (g * 4 + tp) * 4 + half + 2 * bh]
                        = f2tf32(v);
                }
            }
        }

    // stage 3: xOut = hnew @ lin1 (next block's lin1)
    if (lin1 != nullptr) {
        zero_c(c);
        loadB_g(bR, lin1, 0, 128, tid);
        __syncthreads();
        storeB_f(Bs0, bR, tid);
        __syncthreads();
        for (int ch = 0; ch < 4; ch++) {
            if (ch < 3) loadB_g(bR, lin1, (ch + 1) * 32, 128, tid);
            mma_chunk_f<TI_STR>(Tt + ch * 4 * AKT_STR, (ch & 1) ? Bs1 : Bs0, c, wid, lane);
            if (ch < 3) storeB_f(((ch + 1) & 1) ? Bs1 : Bs0, bR, tid);
            __syncthreads();
        }
#pragma unroll
        for (int i = 0; i < 4; i++)
#pragma unroll
            for (int half = 0; half < 2; half++) {
                const int gm = mBase + warpM + i * 16 + g + half * 8;
                if (gm < N_NODES) {
                    float* orow = xOut + (size_t)gm * 128;
#pragma unroll
                    for (int j = 0; j < 4; j++) {
                        const int col = warpN + j * 8 + t * 2;
                        *reinterpret_cast<float2*>(orow + col) =
                            make_float2(c[i][j][half * 2 + 0], c[i][j][half * 2 + 1]);
                    }
                }
            }
    }
}

// ---------------- plain GEMM (initial x = h @ lin1_0) ----------------
__global__ void __launch_bounds__(256, 1) gemm_plain(
    const float* __restrict__ A, const float* __restrict__ B,
    float* __restrict__ out, int M)
{
    extern __shared__ uint32_t sm[];
    uint32_t* As0 = sm;
    uint32_t* As1 = As0 + AWORDS;
    uint32_t* Bs0 = As1 + AWORDS;
    uint32_t* Bs1 = Bs0 + BWORDS;

    const int tid = threadIdx.x;
    const int wid = tid >> 5, lane = tid & 31;
    const int g = lane >> 2, t = lane & 3;
    const int warpM = (wid & 1) * 64, warpN = (wid >> 1) * 32;
    const int mBase = blockIdx.x * 128;

    float c[4][4][4];
    zero_c(c);
    float4 aR[4], bR[4];
    loadA_g(aR, A, mBase, 0, M, 128, tid);
    loadB_g(bR, B, 0, 128, tid);
    storeA_f(As0, aR, tid);
    storeB_f(Bs0, bR, tid);
    __syncthreads();
    for (int ch = 0; ch < 4; ch++) {
        if (ch < 3) {
            loadA_g(aR, A, mBase, (ch + 1) * 32, M, 128, tid);
            loadB_g(bR, B, (ch + 1) * 32, 128, tid);
        }
        mma_chunk_f<AI_STR>((ch & 1) ? As1 : As0, (ch & 1) ? Bs1 : Bs0, c, wid, lane);
        if (ch < 3) {
            storeA_f(((ch + 1) & 1) ? As1 : As0, aR, tid);
            storeB_f(((ch + 1) & 1) ? Bs1 : Bs0, bR, tid);
        }
        __syncthreads();
    }
#pragma unroll
    for (int i = 0; i < 4; i++)
#pragma unroll
        for (int half = 0; half < 2; half++) {
            const int gm = mBase + warpM + i * 16 + g + half * 8;
            if (gm < M) {
                float* orow = out + (size_t)gm * 128;
#pragma unroll
                for (int j = 0; j < 4; j++) {
                    const int col = warpN + j * 8 + t * 2;
                    *reinterpret_cast<float2*>(orow + col) =
                        make_float2(c[i][j][half * 2 + 0], c[i][j][half * 2 + 1]);
                }
            }
        }
}

// ---------------- small kernels ----------------
__global__ void embed_kernel(const float* __restrict__ z, const float* __restrict__ w,
                             const float* __restrict__ b, float* __restrict__ h) {
    int n = blockIdx.x, j = threadIdx.x;
    const float* zr = z + (size_t)n * (IN_DIM + HID);
    float acc = b[j] + zr[IN_DIM + j];
#pragma unroll
    for (int k = 0; k < IN_DIM; k++) acc = fmaf(zr[k], w[k * HID + j], acc);
    h[(size_t)n * HID + j] = acc;
}

__global__ void cmask_kernel(const float* __restrict__ len, float* __restrict__ C) {
    int e = blockIdx.x * 256 + threadIdx.x;
    if (e < N_EDGES) {
        float l = len[e];
        C[e] = (l <= 10.0f && l >= 0.0f) ? 1.0f : 0.0f;
    }
}

__global__ void zero_kernel(float4* __restrict__ p, int n4) {
    int i = blockIdx.x * 256 + threadIdx.x;
    if (i < n4) p[i] = make_float4(0.f, 0.f, 0.f, 0.f);
}

// ---------------- host launch ----------------
extern "C" void kernel_launch(void* const* d_in, const int* in_sizes, int n_in,
                              void* d_out, int out_size) {
    const float* z      = (const float*)d_in[0];
    const int*   ei     = (const int*)  d_in[1];
    const float* elen   = (const float*)d_in[2];
    const float* eattr  = (const float*)d_in[3];
    const float* emb_w  = (const float*)d_in[4];
    const float* emb_b  = (const float*)d_in[5];
    const float* lin1_w = (const float*)d_in[6];
    const float* nn_w1  = (const float*)d_in[7];
    const float* nn_b1  = (const float*)d_in[8];
    const float* nn_w2  = (const float*)d_in[9];
    const float* nn_b2  = (const float*)d_in[10];
    const float* lin2_w = (const float*)d_in[11];
    const float* lin2_b = (const float*)d_in[12];
    const float* lin_w  = (const float*)d_in[13];
    const float* lin_b  = (const float*)d_in[14];
    float* h = (float*)d_out;

    float *px, *pagg, *pC;
    cudaGetSymbolAddress((void**)&px,   g_x);
    cudaGetSymbolAddress((void**)&pagg, g_agg);
    cudaGetSymbolAddress((void**)&pC,   g_C);

    cudaFuncSetAttribute(edge_fused, cudaFuncAttributeMaxDynamicSharedMemorySize, FUSED_SMEM);
    cudaFuncSetAttribute(node_fused, cudaFuncAttributeMaxDynamicSharedMemorySize, FUSED_SMEM);
    cudaFuncSetAttribute(gemm_plain, cudaFuncAttributeMaxDynamicSharedMemorySize, PLAIN_SMEM);

    const int* src = ei;
    const int* dst = ei + N_EDGES;

    embed_kernel<<<N_NODES, HID>>>(z, emb_w, emb_b, h);
    cmask_kernel<<<(N_EDGES + 255) / 256, 256>>>(elen, pC);

    const int nodeTiles = (N_NODES + 127) / 128;   // 391
    const int edgeTiles = N_EDGES / 128;           // 6250
    const int aggN4 = N_NODES * HID / 4;

    // initial x = h @ lin1_w[0]
    gemm_plain<<<nodeTiles, 256, PLAIN_SMEM>>>(h, lin1_w, px, N_NODES);

    for (int i = 0; i < N_BLOCKS; i++) {
        zero_kernel<<<(aggN4 + 255) / 256, 256>>>((float4*)pagg, aggN4);
        edge_fused<<<edgeTiles, 256, FUSED_SMEM>>>(
            eattr, nn_w1 + (size_t)i * EC * HID, nn_b1 + (size_t)i * HID,
            nn_w2 + (size_t)i * HID * HID, nn_b2 + (size_t)i * HID,
            pC, src, dst, px, pagg);
        const float* lin1next = (i + 1 < N_BLOCKS) ? (lin1_w + (size_t)(i + 1) * HID * HID) : nullptr;
        node_fused<<<nodeTiles, 256, FUSED_SMEM>>>(
            pagg, lin2_w + (size_t)i * HID * HID, lin2_b + (size_t)i * HID,
            lin_w + (size_t)i * HID * HID, lin_b + (size_t)i * HID,
            h, lin1next, px);
    }
}

// round 6
// speedup vs baseline: 2.0867x; 1.1339x over previous
#include <cuda_runtime.h>
#include <cstdint>
#include <math.h>

#define N_NODES 50000
#define N_EDGES 800000
#define HID 128
#define EC 100
#define IN_DIM 5
#define N_BLOCKS 6
#define NT 512

// ---------------- scratch (device globals; no runtime allocation) ----------------
__device__ float g_x[N_NODES * HID];
__device__ float g_agg[N_NODES * HID];
__device__ float g_C[N_EDGES];

__device__ __forceinline__ float sspf(float x) {
    float sp = fmaxf(x, 0.0f) + log1pf(expf(-fabsf(x)));
    return sp - 0.69314718055994531f;
}

__device__ __forceinline__ uint32_t f2tf32(float f) {
    uint32_t r;
    asm("cvt.rna.tf32.f32 %0, %1;" : "=r"(r) : "f"(f));
    return r;
}

// ---------------- fragment-order smem layout (strides in words) ----------------
// A-frag chunk: [i-tile 0..7][kt 0..3][lane 0..31][w 0..3]
// B-frag chunk: [pair 0..7][kt 0..3][lane 0..31][w 0..3]
// T-frag tile:  [i-tile 0..7][kt 0..15][lane][w]
#define AKT_STR 132
#define AI_STR  528
#define AWORDS  4224
#define BKT_STR 132
#define BP_STR  528
#define BWORDS  4224
#define TI_STR  2112
#define TWORDS  16896

#define FUSED_SMEM ((TWORDS + 2 * AWORDS + 2 * BWORDS) * 4)
#define PLAIN_SMEM ((2 * AWORDS + 2 * BWORDS) * 4)

// ---------------- global->reg loaders (512 threads: 2 float4 each) ----------------
__device__ __forceinline__ void loadA_g(float4* r, const float* __restrict__ A,
                                        int mBase, int k0, int M, int K, int tid) {
#pragma unroll
    for (int i = 0; i < 2; i++) {
        int q = tid + (i << 9);
        int row = q >> 3, kq = (q & 7) << 2;
        int gm = mBase + row, gk = k0 + kq;
        r[i] = make_float4(0.f, 0.f, 0.f, 0.f);
        if (gm < M && gk < K)
            r[i] = *reinterpret_cast<const float4*>(A + (size_t)gm * K + gk);
    }
}
__device__ __forceinline__ void loadB_g(float4* r, const float* __restrict__ B,
                                        int k0, int K, int tid) {
#pragma unroll
    for (int i = 0; i < 2; i++) {
        int q = tid + (i << 9);
        int kr = q >> 5, nq = (q & 31) << 2;
        int gk = k0 + kr;
        r[i] = make_float4(0.f, 0.f, 0.f, 0.f);
        if (gk < K)
            r[i] = *reinterpret_cast<const float4*>(B + (size_t)gk * 128 + nq);
    }
}

// ---------------- reg->smem fragment-order stores ----------------
__device__ __forceinline__ void storeA_f(uint32_t* __restrict__ buf, const float4* r, int tid) {
#pragma unroll
    for (int i4 = 0; i4 < 2; i4++) {
        int q = tid + (i4 << 9);
        int row = q >> 3, kq = (q & 7) << 2;
        int iT = row >> 4, rl = row & 15;
        int g = rl & 7, half = rl >> 3;
        int kt = kq >> 3;
        int w = half + ((kq & 4) ? 2 : 0);
        uint32_t* p = buf + iT * AI_STR + kt * AKT_STR + g * 16 + w;
        p[0]  = f2tf32(r[i4].x);
        p[4]  = f2tf32(r[i4].y);
        p[8]  = f2tf32(r[i4].z);
        p[12] = f2tf32(r[i4].w);
    }
}
__device__ __forceinline__ void storeB_f(uint32_t* __restrict__ buf, const float4* r, int tid) {
#pragma unroll
    for (int i4 = 0; i4 < 2; i4++) {
        int q = tid + (i4 << 9);
        int kr = q >> 5, nq = (q & 31) << 2;
        int kt = kr >> 3, t = kr & 3;
        int bh = (kr & 4) ? 1 : 0;
        int ntile = nq >> 3, g0 = nq & 7;
        int pair = ntile >> 1;
        int w = ((ntile & 1) << 1) + bh;
        uint32_t* p = buf + pair * BP_STR + kt * BKT_STR + (g0 * 4 + t) * 4 + w;
        p[0]  = f2tf32(r[i4].x);
        p[16] = f2tf32(r[i4].y);
        p[32] = f2tf32(r[i4].z);
        p[48] = f2tf32(r[i4].w);
    }
}

// ---------------- one 32-k chunk: c += A(128x32)@B(32x128), warp tile 32x32 -------
template<int ISTR>
__device__ __forceinline__ void mma_chunk_f(const uint32_t* __restrict__ As,
                                            const uint32_t* __restrict__ Bs,
                                            float c[2][4][4], int wid, int lane)
{
    const uint32_t* Ab = As + ((wid & 3) * 2) * ISTR + lane * 4;
    const uint32_t* Bb = Bs + ((wid >> 2) * 2) * BP_STR + lane * 4;
#pragma unroll
    for (int kk = 0; kk < 4; kk++) {
        uint32_t a[2][4], b[4][2];
#pragma unroll
        for (int i = 0; i < 2; i++) {
            uint4 av = *reinterpret_cast<const uint4*>(Ab + i * ISTR + kk * AKT_STR);
            a[i][0] = av.x; a[i][1] = av.y; a[i][2] = av.z; a[i][3] = av.w;
        }
#pragma unroll
        for (int p = 0; p < 2; p++) {
            uint4 bv = *reinterpret_cast<const uint4*>(Bb + p * BP_STR + kk * BKT_STR);
            b[2 * p][0] = bv.x;     b[2 * p][1] = bv.y;
            b[2 * p + 1][0] = bv.z; b[2 * p + 1][1] = bv.w;
        }
#pragma unroll
        for (int i = 0; i < 2; i++)
#pragma unroll
            for (int j = 0; j < 4; j++) {
                asm volatile(
                    "mma.sync.aligned.m16n8k8.row.col.f32.tf32.tf32.f32 "
                    "{%0,%1,%2,%3}, {%4,%5,%6,%7}, {%8,%9}, {%0,%1,%2,%3};\n"
                    : "+f"(c[i][j][0]), "+f"(c[i][j][1]), "+f"(c[i][j][2]), "+f"(c[i][j][3])
                    : "r"(a[i][0]), "r"(a[i][1]), "r"(a[i][2]), "r"(a[i][3]),
                      "r"(b[j][0]), "r"(b[j][1]));
            }
    }
}

__device__ __forceinline__ void zero_c(float c[2][4][4]) {
#pragma unroll
    for (int i = 0; i < 2; i++)
#pragma unroll
        for (int j = 0; j < 4; j++)
#pragma unroll
            for (int v = 0; v < 4; v++) c[i][j][v] = 0.0f;
}

// store epilogue values (optionally ssp) into T fragment layout
__device__ __forceinline__ void store_T_frag(uint32_t* __restrict__ Tt, const float c[2][4][4],
                                             const float* bn, int wid, int g, int t, bool doSsp)
{
    const int iTb = (wid & 3) * 2;
    const int ktb = (wid >> 2) * 4;
#pragma unroll
    for (int i = 0; i < 2; i++)
#pragma unroll
        for (int half = 0; half < 2; half++)
#pragma unroll
            for (int j = 0; j < 4; j++)
#pragma unroll
                for (int d = 0; d < 2; d++) {
                    float v = c[i][j][half * 2 + d] + bn[j * 2 + d];
                    if (doSsp) v = sspf(v);
                    int col7 = t * 2 + d;
                    int tp = col7 & 3, bh = col7 >> 2;
                    Tt[(iTb + i) * TI_STR + (ktb + j) * AKT_STR + (g * 4 + tp) * 4 + half + 2 * bh]
                        = f2tf32(v);
                }
}

// ---------------- fused edge kernel: GEMM+ssp+GEMM+mask + scatter -----------------
__global__ void __launch_bounds__(NT, 1) edge_fused(
    const float* __restrict__ eattr, const float* __restrict__ B1, const float* __restrict__ b1,
    const float* __restrict__ B2, const float* __restrict__ b2,
    const float* __restrict__ Cm, const int* __restrict__ src, const int* __restrict__ dst,
    const float* __restrict__ x, float* __restrict__ agg)
{
    extern __shared__ uint32_t sm[];
    uint32_t* Tt  = sm;
    uint32_t* As0 = sm + TWORDS;
    uint32_t* As1 = As0 + AWORDS;
    uint32_t* Bs0 = As1 + AWORDS;
    uint32_t* Bs1 = Bs0 + BWORDS;

    const int tid = threadIdx.x;
    const int wid = tid >> 5, lane = tid & 31;
    const int g = lane >> 2, t = lane & 3;
    const int warpM = (wid & 3) * 32, warpN = (wid >> 2) * 32;
    const int mBase = blockIdx.x * 128;

    float c[2][4][4];
    zero_c(c);
    float4 aR[2], bR[2];

    // stage 1 (K=EC=100 -> 4 chunks), double buffered
    loadA_g(aR, eattr, mBase, 0, N_EDGES, EC, tid);
    loadB_g(bR, B1, 0, EC, tid);
    storeA_f(As0, aR, tid);
    storeB_f(Bs0, bR, tid);
    __syncthreads();
    for (int ch = 0; ch < 4; ch++) {
        if (ch < 3) {
            loadA_g(aR, eattr, mBase, (ch + 1) * 32, N_EDGES, EC, tid);
            loadB_g(bR, B1, (ch + 1) * 32, EC, tid);
        }
        mma_chunk_f<AI_STR>((ch & 1) ? As1 : As0, (ch & 1) ? Bs1 : Bs0, c, wid, lane);
        if (ch < 3) {
            storeA_f(((ch + 1) & 1) ? As1 : As0, aR, tid);
            storeB_f(((ch + 1) & 1) ? Bs1 : Bs0, bR, tid);
        }
        __syncthreads();
    }

    float bn1[8];
#pragma unroll
    for (int j = 0; j < 4; j++) {
        bn1[j * 2 + 0] = __ldg(b1 + warpN + j * 8 + t * 2 + 0);
        bn1[j * 2 + 1] = __ldg(b1 + warpN + j * 8 + t * 2 + 1);
    }
    store_T_frag(Tt, c, bn1, wid, g, t, true);
    zero_c(c);

    // stage 2: T (resident) @ B2
    loadB_g(bR, B2, 0, 128, tid);
    __syncthreads();
    storeB_f(Bs0, bR, tid);
    __syncthreads();
    for (int ch = 0; ch < 4; ch++) {
        if (ch < 3) loadB_g(bR, B2, (ch + 1) * 32, 128, tid);
        mma_chunk_f<TI_STR>(Tt + ch * 4 * AKT_STR, (ch & 1) ? Bs1 : Bs0, c, wid, lane);
        if (ch < 3) storeB_f(((ch + 1) & 1) ? Bs1 : Bs0, bR, tid);
        __syncthreads();
    }

    // scatter epilogue: no W materialization
    float bn2[8];
#pragma unroll
    for (int j = 0; j < 4; j++) {
        bn2[j * 2 + 0] = __ldg(b2 + warpN + j * 8 + t * 2 + 0);
        bn2[j * 2 + 1] = __ldg(b2 + warpN + j * 8 + t * 2 + 1);
    }
#pragma unroll
    for (int i = 0; i < 2; i++)
#pragma unroll
        for (int half = 0; half < 2; half++) {
            const int e = mBase + warpM + i * 16 + g + half * 8;
            const float cmv = __ldg(Cm + e);
            if (cmv != 0.0f) {
                const int s = __ldg(src + e), d = __ldg(dst + e);
                const float* xr = x + (size_t)s * 128;
                float* ar = agg + (size_t)d * 128;
#pragma unroll
                for (int j = 0; j < 4; j++) {
                    const int col = warpN + j * 8 + t * 2;
                    float2 xv = *reinterpret_cast<const float2*>(xr + col);
                    float w0 = (c[i][j][half * 2 + 0] + bn2[j * 2 + 0]) * cmv;
                    float w1 = (c[i][j][half * 2 + 1] + bn2[j * 2 + 1]) * cmv;
                    float m0 = xv.x * w0, m1 = xv.y * w1;
                    asm volatile("red.global.add.v2.f32 [%0], {%1, %2};"
                                 :: "l"(ar + col), "f"(m0), "f"(m1) : "memory");
                }
            }
        }
}

// ---------------- fused node kernel ----------------
__global__ void __launch_bounds__(NT, 1) node_fused(
    const float* __restrict__ agg, const float* __restrict__ B1, const float* __restrict__ b1,
    const float* __restrict__ B2, const float* __restrict__ b2,
    float* __restrict__ h, const float* __restrict__ lin1, float* __restrict__ xOut)
{
    extern __shared__ uint32_t sm[];
    uint32_t* Tt  = sm;
    uint32_t* As0 = sm + TWORDS;
    uint32_t* As1 = As0 + AWORDS;
    uint32_t* Bs0 = As1 + AWORDS;
    uint32_t* Bs1 = Bs0 + BWORDS;

    const int tid = threadIdx.x;
    const int wid = tid >> 5, lane = tid & 31;
    const int g = lane >> 2, t = lane & 3;
    const int warpM = (wid & 3) * 32, warpN = (wid >> 2) * 32;
    const int mBase = blockIdx.x * 128;

    float c[2][4][4];
    zero_c(c);
    float4 aR[2], bR[2];

    // stage 1: agg @ B1 (K=128)
    loadA_g(aR, agg, mBase, 0, N_NODES, 128, tid);
    loadB_g(bR, B1, 0, 128, tid);
    storeA_f(As0, aR, tid);
    storeB_f(Bs0, bR, tid);
    __syncthreads();
    for (int ch = 0; ch < 4; ch++) {
        if (ch < 3) {
            loadA_g(aR, agg, mBase, (ch + 1) * 32, N_NODES, 128, tid);
            loadB_g(bR, B1, (ch + 1) * 32, 128, tid);
        }
        mma_chunk_f<AI_STR>((ch & 1) ? As1 : As0, (ch & 1) ? Bs1 : Bs0, c, wid, lane);
        if (ch < 3) {
            storeA_f(((ch + 1) & 1) ? As1 : As0, aR, tid);
            storeB_f(((ch + 1) & 1) ? Bs1 : Bs0, bR, tid);
        }
        __syncthreads();
    }

    float bn1[8];
#pragma unroll
    for (int j = 0; j < 4; j++) {
        bn1[j * 2 + 0] = __ldg(b1 + warpN + j * 8 + t * 2 + 0);
        bn1[j * 2 + 1] = __ldg(b1 + warpN + j * 8 + t * 2 + 1);
    }
    store_T_frag(Tt, c, bn1, wid, g, t, true);
    zero_c(c);

    // stage 2: T @ B2
    loadB_g(bR, B2, 0, 128, tid);
    __syncthreads();
    storeB_f(Bs0, bR, tid);
    __syncthreads();
    for (int ch = 0; ch < 4; ch++) {
        if (ch < 3) loadB_g(bR, B2, (ch + 1) * 32, 128, tid);
        mma_chunk_f<TI_STR>(Tt + ch * 4 * AKT_STR, (ch & 1) ? Bs1 : Bs0, c, wid, lane);
        if (ch < 3) storeB_f(((ch + 1) & 1) ? Bs1 : Bs0, bR, tid);
        __syncthreads();
    }

    // stage-2 epilogue: h += residual; keep hnew resident in T-frag
    float bn2[8];
#pragma unroll
    for (int j = 0; j < 4; j++) {
        bn2[j * 2 + 0] = __ldg(b2 + warpN + j * 8 + t * 2 + 0);
        bn2[j * 2 + 1] = __ldg(b2 + warpN + j * 8 + t * 2 + 1);
    }
    const int iTb = (wid & 3) * 2;
    const int ktb = (wid >> 2) * 4;
#pragma unroll
    for (int i = 0; i < 2; i++)
#pragma unroll
        for (int half = 0; half < 2; half++) {
            const int gm = mBase + warpM + i * 16 + g + half * 8;
            const bool ok = gm < N_NODES;
            float* hrow = h + (size_t)gm * 128;
#pragma unroll
            for (int j = 0; j < 4; j++) {
                const int col = warpN + j * 8 + t * 2;
                float v0 = c[i][j][half * 2 + 0] + bn2[j * 2 + 0];
                float v1 = c[i][j][half * 2 + 1] + bn2[j * 2 + 1];
                if (ok) {
                    float2 hv = *reinterpret_cast<const float2*>(hrow + col);
                    v0 += hv.x; v1 += hv.y;
                    *reinterpret_cast<float2*>(hrow + col) = make_float2(v0, v1);
                }
#pragma unroll
                for (int d = 0; d < 2; d++) {
                    float v = d ? v1 : v0;
                    int col7 = t * 2 + d;
                    int tp = col7 & 3, bh = col7 >> 2;
                    Tt[(iTb + i) * TI_STR + (ktb + j) * AKT_STR + (g * 4 + tp) * 4 + half + 2 * bh]
                        = f2tf32(v);
                }
            }
        }

    // stage 3: xOut = hnew @ lin1 (next block's lin1)
    if (lin1 != nullptr) {
        zero_c(c);
        loadB_g(bR, lin1, 0, 128, tid);
        __syncthreads();
        storeB_f(Bs0, bR, tid);
        __syncthreads();
        for (int ch = 0; ch < 4; ch++) {
            if (ch < 3) loadB_g(bR, lin1, (ch + 1) * 32, 128, tid);
            mma_chunk_f<TI_STR>(Tt + ch * 4 * AKT_STR, (ch & 1) ? Bs1 : Bs0, c, wid, lane);
            if (ch < 3) storeB_f(((ch + 1) & 1) ? Bs1 : Bs0, bR, tid);
            __syncthreads();
        }
#pragma unroll
        for (int i = 0; i < 2; i++)
#pragma unroll
            for (int half = 0; half < 2; half++) {
                const int gm = mBase + warpM + i * 16 + g + half * 8;
                if (gm < N_NODES) {
                    float* orow = xOut + (size_t)gm * 128;
#pragma unroll
                    for (int j = 0; j < 4; j++) {
                        const int col = warpN + j * 8 + t * 2;
                        *reinterpret_cast<float2*>(orow + col) =
                            make_float2(c[i][j][half * 2 + 0], c[i][j][half * 2 + 1]);
                    }
                }
            }
    }
}

// ---------------- plain GEMM (initial x = h @ lin1_0) ----------------
__global__ void __launch_bounds__(NT, 1) gemm_plain(
    const float* __restrict__ A, const float* __restrict__ B,
    float* __restrict__ out, int M)
{
    extern __shared__ uint32_t sm[];
    uint32_t* As0 = sm;
    uint32_t* As1 = As0 + AWORDS;
    uint32_t* Bs0 = As1 + AWORDS;
    uint32_t* Bs1 = Bs0 + BWORDS;

    const int tid = threadIdx.x;
    const int wid = tid >> 5, lane = tid & 31;
    const int g = lane >> 2, t = lane & 3;
    const int warpM = (wid & 3) * 32, warpN = (wid >> 2) * 32;
    const int mBase = blockIdx.x * 128;

    float c[2][4][4];
    zero_c(c);
    float4 aR[2], bR[2];
    loadA_g(aR, A, mBase, 0, M, 128, tid);
    loadB_g(bR, B, 0, 128, tid);
    storeA_f(As0, aR, tid);
    storeB_f(Bs0, bR, tid);
    __syncthreads();
    for (int ch = 0; ch < 4; ch++) {
        if (ch < 3) {
            loadA_g(aR, A, mBase, (ch + 1) * 32, M, 128, tid);
            loadB_g(bR, B, (ch + 1) * 32, 128, tid);
        }
        mma_chunk_f<AI_STR>((ch & 1) ? As1 : As0, (ch & 1) ? Bs1 : Bs0, c, wid, lane);
        if (ch < 3) {
            storeA_f(((ch + 1) & 1) ? As1 : As0, aR, tid);
            storeB_f(((ch + 1) & 1) ? Bs1 : Bs0, bR, tid);
        }
        __syncthreads();
    }
#pragma unroll
    for (int i = 0; i < 2; i++)
#pragma unroll
        for (int half = 0; half < 2; half++) {
            const int gm = mBase + warpM + i * 16 + g + half * 8;
            if (gm < M) {
                float* orow = out + (size_t)gm * 128;
#pragma unroll
                for (int j = 0; j < 4; j++) {
                    const int col = warpN + j * 8 + t * 2;
                    *reinterpret_cast<float2*>(orow + col) =
                        make_float2(c[i][j][half * 2 + 0], c[i][j][half * 2 + 1]);
                }
            }
        }
}

// ---------------- small kernels ----------------
__global__ void embed_kernel(const float* __restrict__ z, const float* __restrict__ w,
                             const float* __restrict__ b, float* __restrict__ h) {
    int n = blockIdx.x, j = threadIdx.x;
    const float* zr = z + (size_t)n * (IN_DIM + HID);
    float acc = b[j] + zr[IN_DIM + j];
#pragma unroll
    for (int k = 0; k < IN_DIM; k++) acc = fmaf(zr[k], w[k * HID + j], acc);
    h[(size_t)n * HID + j] = acc;
}

__global__ void cmask_kernel(const float* __restrict__ len, float* __restrict__ C) {
    int e = blockIdx.x * 256 + threadIdx.x;
    if (e < N_EDGES) {
        float l = len[e];
        C[e] = (l <= 10.0f && l >= 0.0f) ? 1.0f : 0.0f;
    }
}

__global__ void zero_kernel(float4* __restrict__ p, int n4) {
    int i = blockIdx.x * 256 + threadIdx.x;
    if (i < n4) p[i] = make_float4(0.f, 0.f, 0.f, 0.f);
}

// ---------------- host launch ----------------
extern "C" void kernel_launch(void* const* d_in, const int* in_sizes, int n_in,
                              void* d_out, int out_size) {
    const float* z      = (const float*)d_in[0];
    const int*   ei     = (const int*)  d_in[1];
    const float* elen   = (const float*)d_in[2];
    const float* eattr  = (const float*)d_in[3];
    const float* emb_w  = (const float*)d_in[4];
    const float* emb_b  = (const float*)d_in[5];
    const float* lin1_w = (const float*)d_in[6];
    const float* nn_w1  = (const float*)d_in[7];
    const float* nn_b1  = (const float*)d_in[8];
    const float* nn_w2  = (const float*)d_in[9];
    const float* nn_b2  = (const float*)d_in[10];
    const float* lin2_w = (const float*)d_in[11];
    const float* lin2_b = (const float*)d_in[12];
    const float* lin_w  = (const float*)d_in[13];
    const float* lin_b  = (const float*)d_in[14];
    float* h = (float*)d_out;

    float *px, *pagg, *pC;
    cudaGetSymbolAddress((void**)&px,   g_x);
    cudaGetSymbolAddress((void**)&pagg, g_agg);
    cudaGetSymbolAddress((void**)&pC,   g_C);

    cudaFuncSetAttribute(edge_fused, cudaFuncAttributeMaxDynamicSharedMemorySize, FUSED_SMEM);
    cudaFuncSetAttribute(node_fused, cudaFuncAttributeMaxDynamicSharedMemorySize, FUSED_SMEM);
    cudaFuncSetAttribute(gemm_plain, cudaFuncAttributeMaxDynamicSharedMemorySize, PLAIN_SMEM);

    const int* src = ei;
    const int* dst = ei + N_EDGES;

    embed_kernel<<<N_NODES, HID>>>(z, emb_w, emb_b, h);
    cmask_kernel<<<(N_EDGES + 255) / 256, 256>>>(elen, pC);

    const int nodeTiles = (N_NODES + 127) / 128;   // 391
    const int edgeTiles = N_EDGES / 128;           // 6250
    const int aggN4 = N_NODES * HID / 4;

    gemm_plain<<<nodeTiles, NT, PLAIN_SMEM>>>(h, lin1_w, px, N_NODES);

    for (int i = 0; i < N_BLOCKS; i++) {
        zero_kernel<<<(aggN4 + 255) / 256, 256>>>((float4*)pagg, aggN4);
        edge_fused<<<edgeTiles, NT, FUSED_SMEM>>>(
            eattr, nn_w1 + (size_t)i * EC * HID, nn_b1 + (size_t)i * HID,
            nn_w2 + (size_t)i * HID * HID, nn_b2 + (size_t)i * HID,
            pC, src, dst, px, pagg);
        const float* lin1next = (i + 1 < N_BLOCKS) ? (lin1_w + (size_t)(i + 1) * HID * HID) : nullptr;
        node_fused<<<nodeTiles, NT, FUSED_SMEM>>>(
            pagg, lin2_w + (size_t)i * HID * HID, lin2_b + (size_t)i * HID,
            lin_w + (size_t)i * HID * HID, lin_b + (size_t)i * HID,
            h, lin1next, px);
    }
}

// round 7
// speedup vs baseline: 2.9127x; 1.3959x over previous
#include <cuda_runtime.h>
#include <cuda_fp16.h>
#include <cstdint>
#include <math.h>

#define N_NODES 50000
#define N_EDGES 800000
#define HID 128
#define EC 100
#define IN_DIM 5
#define N_BLOCKS 6
#define NT 512

// ---------------- scratch (device globals; no runtime allocation) ----------------
__device__ float g_x[N_NODES * HID];
__device__ float g_agg[N_NODES * HID];
__device__ float g_C[N_EDGES];

__device__ __forceinline__ float sspf(float x) {
    float sp = fmaxf(x, 0.0f) + log1pf(expf(-fabsf(x)));
    return sp - 0.69314718055994531f;
}

// pack two f32 into f16x2 (lo = first arg)
__device__ __forceinline__ uint32_t h2(float lo, float hi) {
    uint32_t r;
    asm("cvt.rn.f16x2.f32 %0, %1, %2;" : "=r"(r) : "f"(hi), "f"(lo));
    return r;
}

// ---------------- fp16 fragment-order smem layout (strides in 32-bit words) -------
// chunk = 32 k = 2 ksteps of m16n8k16.
// A-frag: [i-tile 0..7][ks 0..1][lane 0..31][w 0..3]  w = {a0,a1,a2,a3}
// B-frag: [pair 0..7][ks 0..1][lane 0..31][w 0..3]    w = {j0b0,j0b1,j1b0,j1b1}
// T-frag: [i-tile 0..7][ks 0..7][lane][w]             (resident 128x128 half tile)
#define KS_STR 132
#define AI_STR 264
#define AWORDS 2112
#define BP_STR 264
#define BWORDS 2112
#define TI_STR 1056
#define TWORDS 8448

#define FUSED_SMEM ((TWORDS + 2 * AWORDS + 2 * BWORDS) * 4)
#define PLAIN_SMEM ((2 * AWORDS + 2 * BWORDS) * 4)

// ---------------- global->reg loaders (512 threads: 2 float4 each) ----------------
__device__ __forceinline__ void loadA_g(float4* r, const float* __restrict__ A,
                                        int mBase, int k0, int M, int K, int tid) {
#pragma unroll
    for (int i = 0; i < 2; i++) {
        int q = tid + (i << 9);
        int row = q >> 3, kq = (q & 7) << 2;
        int gm = mBase + row, gk = k0 + kq;
        r[i] = make_float4(0.f, 0.f, 0.f, 0.f);
        if (gm < M && gk < K)
            r[i] = *reinterpret_cast<const float4*>(A + (size_t)gm * K + gk);
    }
}
__device__ __forceinline__ void loadB_g(float4* r, const float* __restrict__ B,
                                        int k0, int K, int tid) {
#pragma unroll
    for (int i = 0; i < 2; i++) {
        int q = tid + (i << 9);
        int kr = q >> 5, nq = (q & 31) << 2;
        int gk = k0 + kr;
        r[i] = make_float4(0.f, 0.f, 0.f, 0.f);
        if (gk < K)
            r[i] = *reinterpret_cast<const float4*>(B + (size_t)gk * 128 + nq);
    }
}

// ---------------- reg->smem fp16 fragment-order stores ----------------
__device__ __forceinline__ void storeA_f(uint32_t* __restrict__ buf, const float4* r, int tid) {
#pragma unroll
    for (int i4 = 0; i4 < 2; i4++) {
        int q = tid + (i4 << 9);
        int row = q >> 3, kq = (q & 7) << 2;       // kq in {0,4,...,28}
        int iT = row >> 4, rl = row & 15;
        int g = rl & 7, hr = rl >> 3;
        int ks = kq >> 4, kl = kq & 15;            // kl in {0,4,8,12}
        int w = hr + ((kl & 8) ? 2 : 0);
        int t0 = (kl & 7) >> 1;                    // 0 or 2
        uint32_t* p = buf + iT * AI_STR + ks * KS_STR + (g * 4 + t0) * 4 + w;
        p[0] = h2(r[i4].x, r[i4].y);               // lane t0
        p[4] = h2(r[i4].z, r[i4].w);               // lane t0+1
    }
}
__device__ __forceinline__ void storeB_f(uint32_t* __restrict__ buf, const float4* r, int tid) {
    __half* hb = reinterpret_cast<__half*>(buf);
#pragma unroll
    for (int i4 = 0; i4 < 2; i4++) {
        int q = tid + (i4 << 9);
        int kr = q >> 5, nq = (q & 31) << 2;
        int ks = kr >> 4, krl = kr & 15;
        int t = (krl & 7) >> 1;
        int hl = krl & 1;
        int wb = (krl >> 3) & 1;
        const float vv[4] = { r[i4].x, r[i4].y, r[i4].z, r[i4].w };
#pragma unroll
        for (int d = 0; d < 4; d++) {
            int n = nq + d;
            int pairI = n >> 4, jpar = (n >> 3) & 1, g0 = n & 7;
            int w = jpar * 2 + wb;
            int word = pairI * BP_STR + ks * KS_STR + (g0 * 4 + t) * 4 + w;
            hb[word * 2 + hl] = __float2half_rn(vv[d]);
        }
    }
}

// ---------------- one 32-k chunk: c += A(128x32)@B(32x128), warp tile 32x32 -------
template<int ISTR>
__device__ __forceinline__ void mma_chunk_f(const uint32_t* __restrict__ As,
                                            const uint32_t* __restrict__ Bs,
                                            float c[2][4][4], int wid, int lane)
{
    const uint32_t* Ab = As + ((wid & 3) * 2) * ISTR + lane * 4;
    const uint32_t* Bb = Bs + ((wid >> 2) * 2) * BP_STR + lane * 4;
#pragma unroll
    for (int ks = 0; ks < 2; ks++) {
        uint4 av[2], bv[2];
#pragma unroll
        for (int i = 0; i < 2; i++)
            av[i] = *reinterpret_cast<const uint4*>(Ab + i * ISTR + ks * KS_STR);
#pragma unroll
        for (int p = 0; p < 2; p++)
            bv[p] = *reinterpret_cast<const uint4*>(Bb + p * BP_STR + ks * KS_STR);
#pragma unroll
        for (int i = 0; i < 2; i++)
#pragma unroll
            for (int j = 0; j < 4; j++) {
                uint32_t b0 = (j & 1) ? bv[j >> 1].z : bv[j >> 1].x;
                uint32_t b1 = (j & 1) ? bv[j >> 1].w : bv[j >> 1].y;
                asm volatile(
                    "mma.sync.aligned.m16n8k16.row.col.f32.f16.f16.f32 "
                    "{%0,%1,%2,%3}, {%4,%5,%6,%7}, {%8,%9}, {%0,%1,%2,%3};\n"
                    : "+f"(c[i][j][0]), "+f"(c[i][j][1]), "+f"(c[i][j][2]), "+f"(c[i][j][3])
                    : "r"(av[i].x), "r"(av[i].y), "r"(av[i].z), "r"(av[i].w),
                      "r"(b0), "r"(b1));
            }
    }
}

__device__ __forceinline__ void zero_c(float c[2][4][4]) {
#pragma unroll
    for (int i = 0; i < 2; i++)
#pragma unroll
        for (int j = 0; j < 4; j++)
#pragma unroll
            for (int v = 0; v < 4; v++) c[i][j][v] = 0.0f;
}

// store epilogue values (optionally ssp) into T fragment layout (half2 words)
__device__ __forceinline__ void store_T_frag(uint32_t* __restrict__ Tt, const float c[2][4][4],
                                             const float* bn, int wid, int g, int t,
                                             int warpN, bool doSsp)
{
    const int iTb = (wid & 3) * 2;
    const int ksBase = warpN >> 4;
#pragma unroll
    for (int i = 0; i < 2; i++)
#pragma unroll
        for (int half = 0; half < 2; half++)
#pragma unroll
            for (int j = 0; j < 4; j++) {
                float v0 = c[i][j][half * 2 + 0] + bn[j * 2 + 0];
                float v1 = c[i][j][half * 2 + 1] + bn[j * 2 + 1];
                if (doSsp) { v0 = sspf(v0); v1 = sspf(v1); }
                int ks = ksBase + (j >> 1);
                int w = half + 2 * (j & 1);
                Tt[(iTb + i) * TI_STR + ks * KS_STR + (g * 4 + t) * 4 + w] = h2(v0, v1);
            }
}

// ---------------- fused edge kernel: GEMM+ssp+GEMM+mask + scatter -----------------
__global__ void __launch_bounds__(NT, 1) edge_fused(
    const float* __restrict__ eattr, const float* __restrict__ B1, const float* __restrict__ b1,
    const float* __restrict__ B2, const float* __restrict__ b2,
    const float* __restrict__ Cm, const int* __restrict__ src, const int* __restrict__ dst,
    const float* __restrict__ x, float* __restrict__ agg)
{
    extern __shared__ uint32_t sm[];
    uint32_t* Tt  = sm;
    uint32_t* As0 = sm + TWORDS;
    uint32_t* As1 = As0 + AWORDS;
    uint32_t* Bs0 = As1 + AWORDS;
    uint32_t* Bs1 = Bs0 + BWORDS;

    const int tid = threadIdx.x;
    const int wid = tid >> 5, lane = tid & 31;
    const int g = lane >> 2, t = lane & 3;
    const int warpM = (wid & 3) * 32, warpN = (wid >> 2) * 32;
    const int mBase = blockIdx.x * 128;

    float c[2][4][4];
    zero_c(c);
    float4 aR[2], bR[2];

    // stage 1 (K=EC=100 -> 4 chunks), double buffered
    loadA_g(aR, eattr, mBase, 0, N_EDGES, EC, tid);
    loadB_g(bR, B1, 0, EC, tid);
    storeA_f(As0, aR, tid);
    storeB_f(Bs0, bR, tid);
    __syncthreads();
    for (int ch = 0; ch < 4; ch++) {
        if (ch < 3) {
            loadA_g(aR, eattr, mBase, (ch + 1) * 32, N_EDGES, EC, tid);
            loadB_g(bR, B1, (ch + 1) * 32, EC, tid);
        }
        mma_chunk_f<AI_STR>((ch & 1) ? As1 : As0, (ch & 1) ? Bs1 : Bs0, c, wid, lane);
        if (ch < 3) {
            storeA_f(((ch + 1) & 1) ? As1 : As0, aR, tid);
            storeB_f(((ch + 1) & 1) ? Bs1 : Bs0, bR, tid);
        }
        __syncthreads();
    }

    float bn1[8];
#pragma unroll
    for (int j = 0; j < 4; j++) {
        bn1[j * 2 + 0] = __ldg(b1 + warpN + j * 8 + t * 2 + 0);
        bn1[j * 2 + 1] = __ldg(b1 + warpN + j * 8 + t * 2 + 1);
    }
    store_T_frag(Tt, c, bn1, wid, g, t, warpN, true);
    zero_c(c);

    // stage 2: T (resident) @ B2
    loadB_g(bR, B2, 0, 128, tid);
    __syncthreads();
    storeB_f(Bs0, bR, tid);
    __syncthreads();
    for (int ch = 0; ch < 4; ch++) {
        if (ch < 3) loadB_g(bR, B2, (ch + 1) * 32, 128, tid);
        mma_chunk_f<TI_STR>(Tt + ch * 2 * KS_STR, (ch & 1) ? Bs1 : Bs0, c, wid, lane);
        if (ch < 3) storeB_f(((ch + 1) & 1) ? Bs1 : Bs0, bR, tid);
        __syncthreads();
    }

    // scatter epilogue: no W materialization
    float bn2[8];
#pragma unroll
    for (int j = 0; j < 4; j++) {
        bn2[j * 2 + 0] = __ldg(b2 + warpN + j * 8 + t * 2 + 0);
        bn2[j * 2 + 1] = __ldg(b2 + warpN + j * 8 + t * 2 + 1);
    }
#pragma unroll
    for (int i = 0; i < 2; i++)
#pragma unroll
        for (int half = 0; half < 2; half++) {
            const int e = mBase + warpM + i * 16 + g + half * 8;
            const float cmv = __ldg(Cm + e);
            if (cmv != 0.0f) {
                const int s = __ldg(src + e), d = __ldg(dst + e);
                const float* xr = x + (size_t)s * 128;
                float* ar = agg + (size_t)d * 128;
#pragma unroll
                for (int j = 0; j < 4; j++) {
                    const int col = warpN + j * 8 + t * 2;
                    float2 xv = *reinterpret_cast<const float2*>(xr + col);
                    float w0 = (c[i][j][half * 2 + 0] + bn2[j * 2 + 0]) * cmv;
                    float w1 = (c[i][j][half * 2 + 1] + bn2[j * 2 + 1]) * cmv;
                    float m0 = xv.x * w0, m1 = xv.y * w1;
                    asm volatile("red.global.add.v2.f32 [%0], {%1, %2};"
                                 :: "l"(ar + col), "f"(m0), "f"(m1) : "memory");
                }
            }
        }
}

// ---------------- fused node kernel ----------------
__global__ void __launch_bounds__(NT, 1) node_fused(
    const float* __restrict__ agg, const float* __restrict__ B1, const float* __restrict__ b1,
    const float* __restrict__ B2, const float* __restrict__ b2,
    float* __restrict__ h, const float* __restrict__ lin1, float* __restrict__ xOut)
{
    extern __shared__ uint32_t sm[];
    uint32_t* Tt  = sm;
    uint32_t* As0 = sm + TWORDS;
    uint32_t* As1 = As0 + AWORDS;
    uint32_t* Bs0 = As1 + AWORDS;
    uint32_t* Bs1 = Bs0 + BWORDS;

    const int tid = threadIdx.x;
    const int wid = tid >> 5, lane = tid & 31;
    const int g = lane >> 2, t = lane & 3;
    const int warpM = (wid & 3) * 32, warpN = (wid >> 2) * 32;
    const int mBase = blockIdx.x * 128;

    float c[2][4][4];
    zero_c(c);
    float4 aR[2], bR[2];

    // stage 1: agg @ B1 (K=128)
    loadA_g(aR, agg, mBase, 0, N_NODES, 128, tid);
    loadB_g(bR, B1, 0, 128, tid);
    storeA_f(As0, aR, tid);
    storeB_f(Bs0, bR, tid);
    __syncthreads();
    for (int ch = 0; ch < 4; ch++) {
        if (ch < 3) {
            loadA_g(aR, agg, mBase, (ch + 1) * 32, N_NODES, 128, tid);
            loadB_g(bR, B1, (ch + 1) * 32, 128, tid);
        }
        mma_chunk_f<AI_STR>((ch & 1) ? As1 : As0, (ch & 1) ? Bs1 : Bs0, c, wid, lane);
        if (ch < 3) {
            storeA_f(((ch + 1) & 1) ? As1 : As0, aR, tid);
            storeB_f(((ch + 1) & 1) ? Bs1 : Bs0, bR, tid);
        }
        __syncthreads();
    }

    float bn1[8];
#pragma unroll
    for (int j = 0; j < 4; j++) {
        bn1[j * 2 + 0] = __ldg(b1 + warpN + j * 8 + t * 2 + 0);
        bn1[j * 2 + 1] = __ldg(b1 + warpN + j * 8 + t * 2 + 1);
    }
    store_T_frag(Tt, c, bn1, wid, g, t, warpN, true);
    zero_c(c);

    // stage 2: T @ B2
    loadB_g(bR, B2, 0, 128, tid);
    __syncthreads();
    storeB_f(Bs0, bR, tid);
    __syncthreads();
    for (int ch = 0; ch < 4; ch++) {
        if (ch < 3) loadB_g(bR, B2, (ch + 1) * 32, 128, tid);
        mma_chunk_f<TI_STR>(Tt + ch * 2 * KS_STR, (ch & 1) ? Bs1 : Bs0, c, wid, lane);
        if (ch < 3) storeB_f(((ch + 1) & 1) ? Bs1 : Bs0, bR, tid);
        __syncthreads();
    }

    // stage-2 epilogue: h += residual; keep hnew resident in T-frag
    float bn2[8];
#pragma unroll
    for (int j = 0; j < 4; j++) {
        bn2[j * 2 + 0] = __ldg(b2 + warpN + j * 8 + t * 2 + 0);
        bn2[j * 2 + 1] = __ldg(b2 + warpN + j * 8 + t * 2 + 1);
    }
    const int iTb = (wid & 3) * 2;
    const int ksBase = warpN >> 4;
#pragma unroll
    for (int i = 0; i < 2; i++)
#pragma unroll
        for (int half = 0; half < 2; half++) {
            const int gm = mBase + warpM + i * 16 + g + half * 8;
            const bool ok = gm < N_NODES;
            float* hrow = h + (size_t)gm * 128;
#pragma unroll
            for (int j = 0; j < 4; j++) {
                const int col = warpN + j * 8 + t * 2;
                float v0 = c[i][j][half * 2 + 0] + bn2[j * 2 + 0];
                float v1 = c[i][j][half * 2 + 1] + bn2[j * 2 + 1];
                if (ok) {
                    float2 hv = *reinterpret_cast<const float2*>(hrow + col);
                    v0 += hv.x; v1 += hv.y;
                    *reinterpret_cast<float2*>(hrow + col) = make_float2(v0, v1);
                }
                int ks = ksBase + (j >> 1);
                int w = half + 2 * (j & 1);
                Tt[(iTb + i) * TI_STR + ks * KS_STR + (g * 4 + t) * 4 + w] = h2(v0, v1);
            }
        }

    // stage 3: xOut = hnew @ lin1 (next block's lin1)
    if (lin1 != nullptr) {
        zero_c(c);
        loadB_g(bR, lin1, 0, 128, tid);
        __syncthreads();
        storeB_f(Bs0, bR, tid);
        __syncthreads();
        for (int ch = 0; ch < 4; ch++) {
            if (ch < 3) loadB_g(bR, lin1, (ch + 1) * 32, 128, tid);
            mma_chunk_f<TI_STR>(Tt + ch * 2 * KS_STR, (ch & 1) ? Bs1 : Bs0, c, wid, lane);
            if (ch < 3) storeB_f(((ch + 1) & 1) ? Bs1 : Bs0, bR, tid);
            __syncthreads();
        }
#pragma unroll
        for (int i = 0; i < 2; i++)
#pragma unroll
            for (int half = 0; half < 2; half++) {
                const int gm = mBase + warpM + i * 16 + g + half * 8;
                if (gm < N_NODES) {
                    float* orow = xOut + (size_t)gm * 128;
#pragma unroll
                    for (int j = 0; j < 4; j++) {
                        const int col = warpN + j * 8 + t * 2;
                        *reinterpret_cast<float2*>(orow + col) =
                            make_float2(c[i][j][half * 2 + 0], c[i][j][half * 2 + 1]);
                    }
                }
            }
    }
}

// ---------------- plain GEMM (initial x = h @ lin1_0) ----------------
__global__ void __launch_bounds__(NT, 1) gemm_plain(
    const float* __restrict__ A, const float* __restrict__ B,
    float* __restrict__ out, int M)
{
    extern __shared__ uint32_t sm[];
    uint32_t* As0 = sm;
    uint32_t* As1 = As0 + AWORDS;
    uint32_t* Bs0 = As1 + AWORDS;
    uint32_t* Bs1 = Bs0 + BWORDS;

    const int tid = threadIdx.x;
    const int wid = tid >> 5, lane = tid & 31;
    const int g = lane >> 2, t = lane & 3;
    const int warpM = (wid & 3) * 32, warpN = (wid >> 2) * 32;
    const int mBase = blockIdx.x * 128;

    float c[2][4][4];
    zero_c(c);
    float4 aR[2], bR[2];
    loadA_g(aR, A, mBase, 0, M, 128, tid);
    loadB_g(bR, B, 0, 128, tid);
    storeA_f(As0, aR, tid);
    storeB_f(Bs0, bR, tid);
    __syncthreads();
    for (int ch = 0; ch < 4; ch++) {
        if (ch < 3) {
            loadA_g(aR, A, mBase, (ch + 1) * 32, M, 128, tid);
            loadB_g(bR, B, (ch + 1) * 32, 128, tid);
        }
        mma_chunk_f<AI_STR>((ch & 1) ? As1 : As0, (ch & 1) ? Bs1 : Bs0, c, wid, lane);
        if (ch < 3) {
            storeA_f(((ch + 1) & 1) ? As1 : As0, aR, tid);
            storeB_f(((ch + 1) & 1) ? Bs1 : Bs0, bR, tid);
        }
        __syncthreads();
    }
#pragma unroll
    for (int i = 0; i < 2; i++)
#pragma unroll
        for (int half = 0; half < 2; half++) {
            const int gm = mBase + warpM + i * 16 + g + half * 8;
            if (gm < M) {
                float* orow = out + (size_t)gm * 128;
#pragma unroll
                for (int j = 0; j < 4; j++) {
                    const int col = warpN + j * 8 + t * 2;
                    *reinterpret_cast<float2*>(orow + col) =
                        make_float2(c[i][j][half * 2 + 0], c[i][j][half * 2 + 1]);
                }
            }
        }
}

// ---------------- small kernels ----------------
__global__ void embed_kernel(const float* __restrict__ z, const float* __restrict__ w,
                             const float* __restrict__ b, float* __restrict__ h) {
    int n = blockIdx.x, j = threadIdx.x;
    const float* zr = z + (size_t)n * (IN_DIM + HID);
    float acc = b[j] + zr[IN_DIM + j];
#pragma unroll
    for (int k = 0; k < IN_DIM; k++) acc = fmaf(zr[k], w[k * HID + j], acc);
    h[(size_t)n * HID + j] = acc;
}

__global__ void cmask_kernel(const float* __restrict__ len, float* __restrict__ C) {
    int e = blockIdx.x * 256 + threadIdx.x;
    if (e < N_EDGES) {
        float l = len[e];
        C[e] = (l <= 10.0f && l >= 0.0f) ? 1.0f : 0.0f;
    }
}

__global__ void zero_kernel(float4* __restrict__ p, int n4) {
    int i = blockIdx.x * 256 + threadIdx.x;
    if (i < n4) p[i] = make_float4(0.f, 0.f, 0.f, 0.f);
}

// ---------------- host launch ----------------
extern "C" void kernel_launch(void* const* d_in, const int* in_sizes, int n_in,
                              void* d_out, int out_size) {
    const float* z      = (const float*)d_in[0];
    const int*   ei     = (const int*)  d_in[1];
    const float* elen   = (const float*)d_in[2];
    const float* eattr  = (const float*)d_in[3];
    const float* emb_w  = (const float*)d_in[4];
    const float* emb_b  = (const float*)d_in[5];
    const float* lin1_w = (const float*)d_in[6];
    const float* nn_w1  = (const float*)d_in[7];
    const float* nn_b1  = (const float*)d_in[8];
    const float* nn_w2  = (const float*)d_in[9];
    const float* nn_b2  = (const float*)d_in[10];
    const float* lin2_w = (const float*)d_in[11];
    const float* lin2_b = (const float*)d_in[12];
    const float* lin_w  = (const float*)d_in[13];
    const float* lin_b  = (const float*)d_in[14];
    float* h = (float*)d_out;

    float *px, *pagg, *pC;
    cudaGetSymbolAddress((void**)&px,   g_x);
    cudaGetSymbolAddress((void**)&pagg, g_agg);
    cudaGetSymbolAddress((void**)&pC,   g_C);

    cudaFuncSetAttribute(edge_fused, cudaFuncAttributeMaxDynamicSharedMemorySize, FUSED_SMEM);
    cudaFuncSetAttribute(node_fused, cudaFuncAttributeMaxDynamicSharedMemorySize, FUSED_SMEM);
    cudaFuncSetAttribute(gemm_plain, cudaFuncAttributeMaxDynamicSharedMemorySize, PLAIN_SMEM);

    const int* src = ei;
    const int* dst = ei + N_EDGES;

    embed_kernel<<<N_NODES, HID>>>(z, emb_w, emb_b, h);
    cmask_kernel<<<(N_EDGES + 255) / 256, 256>>>(elen, pC);

    const int nodeTiles = (N_NODES + 127) / 128;   // 391
    const int edgeTiles = N_EDGES / 128;           // 6250
    const int aggN4 = N_NODES * HID / 4;

    gemm_plain<<<nodeTiles, NT, PLAIN_SMEM>>>(h, lin1_w, px, N_NODES);

    for (int i = 0; i < N_BLOCKS; i++) {
        zero_kernel<<<(aggN4 + 255) / 256, 256>>>((float4*)pagg, aggN4);
        edge_fused<<<edgeTiles, NT, FUSED_SMEM>>>(
            eattr, nn_w1 + (size_t)i * EC * HID, nn_b1 + (size_t)i * HID,
            nn_w2 + (size_t)i * HID * HID, nn_b2 + (size_t)i * HID,
            pC, src, dst, px, pagg);
        const float* lin1next = (i + 1 < N_BLOCKS) ? (lin1_w + (size_t)(i + 1) * HID * HID) : nullptr;
        node_fused<<<nodeTiles, NT, FUSED_SMEM>>>(
            pagg, lin2_w + (size_t)i * HID * HID, lin2_b + (size_t)i * HID,
            lin_w + (size_t)i * HID * HID, lin_b + (size_t)i * HID,
            h, lin1next, px);
    }
}